// round 14
// baseline (speedup 1.0000x reference)
#include <cuda_runtime.h>
#include <cuda_fp16.h>
#include <cstdint>
#include <math.h>

// Problem constants
#define BB 2
#define SS 2048
#define HH 16
#define DD 128
#define NSTATE 2048
#define QKV_W (3*HH*DD)   // 6144

// ---------------- scratch (device globals; no runtime alloc) ----------------
__device__ __half g_attnh[(size_t)BB * SS * HH * DD]; // attn out, half
__device__ __half g_xh[(size_t)BB * SS * NSTATE];     // x half
__device__ __half g_wqh[(size_t)QKV_W * NSTATE];      // W_qkv half
__device__ __half g_woh[(size_t)NSTATE * NSTATE];     // W_o half
__device__ __half g_qh[(size_t)BB * HH * SS * DD];    // q half prescaled [B,H,S,D]
__device__ __half g_kh[(size_t)BB * HH * SS * DD];    // k half [B,H,S,D]
__device__ __half g_vh[(size_t)BB * HH * SS * DD];    // v half [B,H,S,D]

// ---------------- helpers ----------------------------------------------------
__device__ __forceinline__ uint32_t smem_u32(const void* p) {
    uint32_t a;
    asm("{ .reg .u64 t; cvta.to.shared.u64 t, %1; cvt.u32.u64 %0, t; }"
        : "=r"(a) : "l"(p));
    return a;
}
__device__ __forceinline__ void mma_f16(float* c, const uint32_t* a,
                                        const uint32_t* b) {
    asm volatile(
        "mma.sync.aligned.m16n8k16.row.col.f32.f16.f16.f32 "
        "{%0,%1,%2,%3}, {%4,%5,%6,%7}, {%8,%9}, {%0,%1,%2,%3};\n"
        : "+f"(c[0]), "+f"(c[1]), "+f"(c[2]), "+f"(c[3])
        : "r"(a[0]), "r"(a[1]), "r"(a[2]), "r"(a[3]), "r"(b[0]), "r"(b[1]));
}
__device__ __forceinline__ void ldsm_x4(uint32_t* r, uint32_t addr) {
    asm volatile("ldmatrix.sync.aligned.m8n8.x4.shared.b16 {%0,%1,%2,%3}, [%4];"
                 : "=r"(r[0]), "=r"(r[1]), "=r"(r[2]), "=r"(r[3]) : "r"(addr));
}
__device__ __forceinline__ void ldsm_x4_t(uint32_t* r, uint32_t addr) {
    asm volatile("ldmatrix.sync.aligned.m8n8.x4.trans.shared.b16 {%0,%1,%2,%3}, [%4];"
                 : "=r"(r[0]), "=r"(r[1]), "=r"(r[2]), "=r"(r[3]) : "r"(addr));
}
__device__ __forceinline__ void cp16(uint32_t s, const void* g) {
    asm volatile("cp.async.cg.shared.global [%0], [%1], 16;"
                 :: "r"(s), "l"(g) : "memory");
}
__device__ __forceinline__ uint32_t h2bits(__half2 h) {
    return *(uint32_t*)&h;
}
#define CP_COMMIT() asm volatile("cp.async.commit_group;" ::: "memory")
#define CP_WAIT2()  asm volatile("cp.async.wait_group 2;"  ::: "memory")
#define CP_WAIT0()  asm volatile("cp.async.wait_group 0;"  ::: "memory")

// ---------------- fp32 -> fp16 pre-round pass --------------------------------
__global__ void round_half(const float* __restrict__ src,
                           __half* __restrict__ dst, int n4) {
    int i = blockIdx.x * blockDim.x + threadIdx.x;
    if (i >= n4) return;
    float4 v = ((const float4*)src)[i];
    __half2 h0 = __floats2half2_rn(v.x, v.y);
    __half2 h1 = __floats2half2_rn(v.z, v.w);
    uint2 o = { *(uint32_t*)&h0, *(uint32_t*)&h1 };
    ((uint2*)dst)[i] = o;
}

// ============================================================================
// Shared GEMM config: block 128x128, BK=32 halves, 4 warps (2x2), 64x64 warp
// tiles, 4-stage cp.async ring, TPH=40 rows, ldmatrix. 2 CTAs/SM, 128 thr.
// ============================================================================
#define TPH 40                                // halves; 80B row (5x16B, odd)
#define G_NSTG 4
#define G_AB (128 * TPH * 2)                  // 10240 B per operand tile
#define G_STG (2 * G_AB)                      // 20480 B per stage
#define G_SMEM (G_NSTG * G_STG)               // 81920 B

__device__ __forceinline__ void gemm_issue(uint32_t sbase,
                                           const __half* __restrict__ A,
                                           const __half* __restrict__ B,
                                           int m0, int n0, int K, int k0,
                                           int tid) {
#pragma unroll
    for (int j = 0; j < 4; j++) {               // 512 chunks of A
        int t = tid + j * 128;
        int row = t >> 2, seg = t & 3;
        cp16(sbase + (uint32_t)(row * TPH + seg * 8) * 2,
             &A[(size_t)(m0 + row) * K + k0 + seg * 8]);
    }
    const uint32_t sB = sbase + G_AB;
#pragma unroll
    for (int j = 0; j < 4; j++) {               // 512 chunks of B
        int t = tid + j * 128;
        int row = t >> 2, seg = t & 3;
        cp16(sB + (uint32_t)(row * TPH + seg * 8) * 2,
             &B[(size_t)(n0 + row) * K + k0 + seg * 8]);
    }
}

// Mainloop body shared by both GEMMs (acc[4][8][4] in caller's registers)
#define GEMM_MAINLOOP(A, B, m0, n0, K)                                        \
    const int NC = (K) / 32;                                                  \
    _Pragma("unroll")                                                         \
    for (int s = 0; s < G_NSTG - 1; s++) {                                    \
        gemm_issue(sb + s * G_STG, A, B, m0, n0, K, s * 32, tid);             \
        CP_COMMIT();                                                          \
    }                                                                         \
    for (int c = 0; c < NC; c++) {                                            \
        CP_WAIT2();                                                           \
        __syncthreads();                                                      \
        const int nc = c + G_NSTG - 1;                                        \
        if (nc < NC)                                                          \
            gemm_issue(sb + (nc % G_NSTG) * G_STG, A, B, m0, n0, K,           \
                       nc * 32, tid);                                         \
        CP_COMMIT();                                                          \
        const uint32_t st = sb + (c % G_NSTG) * G_STG;                        \
        _Pragma("unroll")                                                     \
        for (int kk = 0; kk < 2; kk++) {                                      \
            uint32_t af[4][4];                                                \
            _Pragma("unroll")                                                 \
            for (int mt = 0; mt < 4; mt++)                                    \
                ldsm_x4(af[mt], st + aOff + kk * 32 + mt * (16 * TPH * 2));   \
            _Pragma("unroll")                                                 \
            for (int p = 0; p < 4; p++) {                                     \
                uint32_t r[4];                                                \
                ldsm_x4(r, st + bOff + kk * 32 + p * (16 * TPH * 2));         \
                _Pragma("unroll")                                             \
                for (int mt = 0; mt < 4; mt++) {                              \
                    mma_f16(acc[mt][2 * p],     af[mt], r);                   \
                    mma_f16(acc[mt][2 * p + 1], af[mt], r + 2);               \
                }                                                             \
            }                                                                 \
        }                                                                     \
    }

// ============================================================================
// Output-projection GEMM (NT): C fp32 = A @ B^T
// ============================================================================
__global__ __launch_bounds__(128, 2)
void gemm_mma(const __half* __restrict__ A, const __half* __restrict__ B,
              float* __restrict__ C, int M, int N, int K) {
    extern __shared__ uint32_t dynsm[];
    const uint32_t sb = smem_u32(dynsm);

    const int tid = threadIdx.x;
    const int w = tid >> 5, l = tid & 31;
    const int lr = l >> 2, lc = l & 3;
    const int wm = w >> 1, wn = w & 1;
    const int m0 = blockIdx.y * 128, n0 = blockIdx.x * 128;
    const int mat = l >> 3;

    const uint32_t aOff = (uint32_t)(((wm * 64 + (mat & 1) * 8 + (l & 7)) * TPH)
                                     + (mat >> 1) * 8) * 2;
    const uint32_t bOff = G_AB
                        + (uint32_t)(((wn * 64 + (mat >> 1) * 8 + (l & 7)) * TPH)
                                     + (mat & 1) * 8) * 2;

    float acc[4][8][4];
#pragma unroll
    for (int mt = 0; mt < 4; mt++)
#pragma unroll
        for (int nt = 0; nt < 8; nt++)
#pragma unroll
            for (int i = 0; i < 4; i++) acc[mt][nt][i] = 0.f;

    GEMM_MAINLOOP(A, B, m0, n0, K)

#pragma unroll
    for (int mt = 0; mt < 4; mt++) {
        int m = m0 + wm * 64 + mt * 16 + lr;
#pragma unroll
        for (int nt = 0; nt < 8; nt++) {
            int n = n0 + wn * 64 + nt * 8 + lc * 2;
            float2 v0 = { acc[mt][nt][0], acc[mt][nt][1] };
            float2 v1 = { acc[mt][nt][2], acc[mt][nt][3] };
            *(float2*)&C[(size_t)m * N + n] = v0;
            *(float2*)&C[(size_t)(m + 8) * N + n] = v1;
        }
    }
}

// ============================================================================
// QKV GEMM with fused bias + RoPE epilogue.
// N-tile = one head of one stream: sel = bx>>4 (0=q,1=k,2=v), h = bx&15.
// Epilogue stages the fp32 tile in smem, rotates (d, d+64) pairs, writes:
//   q -> g_qh (prescaled half, head-major)
//   k -> out_k fp32 [B,S,H,D] + g_kh (half, head-major)
//   v -> out_v fp32 [B,S,H,D] + g_vh (half, head-major)
// ============================================================================
#define CSTR 132   // fp32 stage row stride

__global__ __launch_bounds__(128, 2)
void gemm_qkv_rope(const __half* __restrict__ A, const __half* __restrict__ B,
                   const float* __restrict__ bias,
                   const float* __restrict__ f_r, const float* __restrict__ f_i,
                   float* __restrict__ out_k, float* __restrict__ out_v,
                   __half* __restrict__ qh, __half* __restrict__ kh,
                   __half* __restrict__ vh) {
    extern __shared__ uint32_t dynsm[];
    const uint32_t sb = smem_u32(dynsm);
    const int K = NSTATE;

    const int tid = threadIdx.x;
    const int w = tid >> 5, l = tid & 31;
    const int lr = l >> 2, lc = l & 3;
    const int wm = w >> 1, wn = w & 1;
    const int m0 = blockIdx.y * 128, n0 = blockIdx.x * 128;
    const int sel = blockIdx.x >> 4;             // 0=q, 1=k, 2=v
    const int h   = blockIdx.x & 15;
    const int mat = l >> 3;

    const uint32_t aOff = (uint32_t)(((wm * 64 + (mat & 1) * 8 + (l & 7)) * TPH)
                                     + (mat >> 1) * 8) * 2;
    const uint32_t bOff = G_AB
                        + (uint32_t)(((wn * 64 + (mat >> 1) * 8 + (l & 7)) * TPH)
                                     + (mat & 1) * 8) * 2;

    float acc[4][8][4];
#pragma unroll
    for (int mt = 0; mt < 4; mt++)
#pragma unroll
        for (int nt = 0; nt < 8; nt++)
#pragma unroll
            for (int i = 0; i < 4; i++) acc[mt][nt][i] = 0.f;

    GEMM_MAINLOOP(A, B, m0, n0, K)

    // ---- epilogue: bias, stage fp32 tile to smem ----
    __syncthreads();                  // all warps done reading last stage
    float* Ct = (float*)dynsm;        // [128][CSTR]
#pragma unroll
    for (int mt = 0; mt < 4; mt++) {
        int ml = wm * 64 + mt * 16 + lr;
#pragma unroll
        for (int nt = 0; nt < 8; nt++) {
            int nl = wn * 64 + nt * 8 + lc * 2;
            float bx = bias[n0 + nl], by = bias[n0 + nl + 1];
            Ct[ml * CSTR + nl]           = acc[mt][nt][0] + bx;
            Ct[ml * CSTR + nl + 1]       = acc[mt][nt][1] + by;
            Ct[(ml + 8) * CSTR + nl]     = acc[mt][nt][2] + bx;
            Ct[(ml + 8) * CSTR + nl + 1] = acc[mt][nt][3] + by;
        }
    }
    __syncthreads();

    // ---- rope + scatter: thread (r0, d2) handles rows r0, r0+2, ... ----
    const float scale = 0.08838834764831845f;    // 1/sqrt(128)
    const int d2 = tid & 63;
    const int r0 = tid >> 6;                     // 0 or 1
#pragma unroll 4
    for (int rr = 0; rr < 64; rr++) {
        int r = r0 + 2 * rr;
        int bs = m0 + r;
        int b = bs >> 11, s = bs & (SS - 1);
        float c0 = Ct[r * CSTR + d2];
        float c1 = Ct[r * CSTR + d2 + 64];
        size_t hmaj = (((size_t)(b * HH + h) * SS) + s) * DD + d2;
        if (sel == 0) {
            float fr = f_r[(size_t)bs * 64 + d2];
            float fi = f_i[(size_t)bs * 64 + d2];
            qh[hmaj]      = __float2half_rn((c0 * fr - c1 * fi) * scale);
            qh[hmaj + 64] = __float2half_rn((c0 * fi + c1 * fr) * scale);
        } else if (sel == 1) {
            float fr = f_r[(size_t)bs * 64 + d2];
            float fi = f_i[(size_t)bs * 64 + d2];
            float klo = c0 * fr - c1 * fi;
            float khi = c0 * fi + c1 * fr;
            size_t ko = ((size_t)bs * HH + h) * DD + d2;
            out_k[ko]      = klo;
            out_k[ko + 64] = khi;
            kh[hmaj]      = __float2half_rn(klo);
            kh[hmaj + 64] = __float2half_rn(khi);
        } else {
            size_t ko = ((size_t)bs * HH + h) * DD + d2;
            out_v[ko]      = c0;
            out_v[ko + 64] = c1;
            vh[hmaj]      = __float2half_rn(c0);
            vh[hmaj + 64] = __float2half_rn(c1);
        }
    }
}

// ============================================================================
// Flash attention, fp16 mma.sync + ldmatrix(+trans for V) + cp.async.
// BM=128 (8 warps x 16), BN=128. Q/K/V all half head-major [B,H,S,D].
// Q fragments hoisted; P register-resident. Causal; heavy tiles first.
// ============================================================================
#define FSTR 136   // halves: row stride (272B, odd 16B count)
#define FA_KB   (128 * FSTR)             // K stage, halves
#define FA_VB   (128 * FSTR)             // V stage, halves
#define FA_BYTES ((128*FSTR /*Q*/ + 2*FA_KB + 2*FA_VB) * 2)   // 174080 B

__global__ __launch_bounds__(256, 1)
void flash_attn(const __half* __restrict__ qh,
                const __half* __restrict__ kh,
                const __half* __restrict__ vh,
                const float* __restrict__ mask,
                __half* __restrict__ attn_out) {
    extern __shared__ __half smh[];
    __half* Qs  = smh;                    // [128][FSTR]
    __half* Ks0 = Qs + 128 * FSTR;        // [2][128][FSTR]  rows = kv pos
    __half* Vs0 = Ks0 + 2 * FA_KB;        // [2][128][FSTR]  rows = kv pos

    const int qb = (int)gridDim.x - 1 - (int)blockIdx.x;
    const int h = blockIdx.y, b = blockIdx.z;
    const int tid = threadIdx.x, w = tid >> 5, l = tid & 31;
    const int lr = l >> 2, lc = l & 3;

    const int mat = l >> 3;
    const uint32_t sQ = smem_u32(Qs), sK = smem_u32(Ks0);
    const uint32_t sV = smem_u32(Vs0);
    const uint32_t qFrag = sQ + (uint32_t)(((w * 16 + (mat & 1) * 8 + (l & 7)) * FSTR)
                                           + (mat >> 1) * 8) * 2;
    const uint32_t kFrag = sK + (uint32_t)((((mat >> 1) * 8 + (l & 7)) * FSTR)
                                           + (mat & 1) * 8) * 2;
    const uint32_t vFrag = sV + (uint32_t)((((mat & 1) * 8 + (l & 7)) * FSTR)
                                           + (mat >> 1) * 8) * 2;

    const __half* qrh = qh + ((size_t)(b * HH + h) * SS) * DD;
    const __half* krh = kh + ((size_t)(b * HH + h) * SS) * DD;
    const __half* vrh = vh + ((size_t)(b * HH + h) * SS) * DD;

    auto issue_kv = [&](int buf, int kb) {
        const uint32_t kBase = sK + (uint32_t)buf * (FA_KB * 2);
        const uint32_t vBase = sV + (uint32_t)buf * (FA_VB * 2);
#pragma unroll
        for (int j = 0; j < 8; j++) {
            int t = tid + j * 256;
            int r = t >> 4, c8 = t & 15;
            cp16(kBase + (uint32_t)(r * FSTR + c8 * 8) * 2,
                 &krh[(size_t)(kb * 128 + r) * DD + c8 * 8]);
        }
#pragma unroll
        for (int j = 0; j < 8; j++) {
            int t = tid + j * 256;
            int r = t >> 4, c8 = t & 15;
            cp16(vBase + (uint32_t)(r * FSTR + c8 * 8) * 2,
                 &vrh[(size_t)(kb * 128 + r) * DD + c8 * 8]);
        }
    };

#pragma unroll
    for (int j = 0; j < 8; j++) {
        int t = tid + j * 256;
        int r = t >> 4, c8 = t & 15;
        cp16(sQ + (uint32_t)(r * FSTR + c8 * 8) * 2,
             &qrh[(size_t)(qb * 128 + r) * DD + c8 * 8]);
    }
    CP_COMMIT();
    issue_kv(0, 0);
    CP_COMMIT();
    CP_WAIT0();
    __syncthreads();

    uint32_t qf[8][4];
#pragma unroll
    for (int ks = 0; ks < 8; ks++)
        ldsm_x4(qf[ks], qFrag + ks * 32);

    float O[16][4];
#pragma unroll
    for (int nt = 0; nt < 16; nt++)
#pragma unroll
        for (int i = 0; i < 4; i++) O[nt][i] = 0.f;
    float m_lo = -INFINITY, m_hi = -INFINITY, l_lo = 0.f, l_hi = 0.f;

    const int nKV = qb + 1;

    for (int kb = 0; kb < nKV; kb++) {
        const int buf = kb & 1;
        if (kb > 0) {
            CP_WAIT0();
            __syncthreads();
        }
        if (kb + 1 < nKV) {
            issue_kv(buf ^ 1, kb + 1);
            CP_COMMIT();
        }

        const uint32_t kOff = (uint32_t)buf * (FA_KB * 2);
        const uint32_t vOff = (uint32_t)buf * (FA_VB * 2);

        float S[16][4];
#pragma unroll
        for (int nt = 0; nt < 16; nt++)
#pragma unroll
            for (int i = 0; i < 4; i++) S[nt][i] = 0.f;
#pragma unroll
        for (int ks = 0; ks < 8; ks++) {
#pragma unroll
            for (int p = 0; p < 8; p++) {
                uint32_t r[4];
                ldsm_x4(r, kFrag + kOff + ks * 32 + p * (16 * FSTR * 2));
                mma_f16(S[2 * p], qf[ks], r);
                mma_f16(S[2 * p + 1], qf[ks], r + 2);
            }
        }

        if (kb == qb) {
            const int m_glo = qb * 128 + w * 16 + lr;
            const float* mr0 = &mask[((size_t)b * SS + m_glo) * SS + kb * 128];
            const float* mr1 = mr0 + 8 * SS;
#pragma unroll
            for (int nt = 0; nt < 16; nt++) {
                float2 q0 = *(const float2*)&mr0[nt * 8 + lc * 2];
                float2 q1 = *(const float2*)&mr1[nt * 8 + lc * 2];
                S[nt][0] += q0.x; S[nt][1] += q0.y;
                S[nt][2] += q1.x; S[nt][3] += q1.y;
            }
        }

        float bm_lo = -INFINITY, bm_hi = -INFINITY;
#pragma unroll
        for (int nt = 0; nt < 16; nt++) {
            bm_lo = fmaxf(bm_lo, fmaxf(S[nt][0], S[nt][1]));
            bm_hi = fmaxf(bm_hi, fmaxf(S[nt][2], S[nt][3]));
        }
        bm_lo = fmaxf(bm_lo, __shfl_xor_sync(0xffffffff, bm_lo, 1));
        bm_lo = fmaxf(bm_lo, __shfl_xor_sync(0xffffffff, bm_lo, 2));
        bm_hi = fmaxf(bm_hi, __shfl_xor_sync(0xffffffff, bm_hi, 1));
        bm_hi = fmaxf(bm_hi, __shfl_xor_sync(0xffffffff, bm_hi, 2));
        float mn_lo = fmaxf(m_lo, bm_lo);
        float mn_hi = fmaxf(m_hi, bm_hi);

        float rs_lo = 0.f, rs_hi = 0.f;
#pragma unroll
        for (int nt = 0; nt < 16; nt++) {
            S[nt][0] = __expf(S[nt][0] - mn_lo);
            S[nt][1] = __expf(S[nt][1] - mn_lo);
            S[nt][2] = __expf(S[nt][2] - mn_hi);
            S[nt][3] = __expf(S[nt][3] - mn_hi);
            rs_lo += S[nt][0] + S[nt][1];
            rs_hi += S[nt][2] + S[nt][3];
        }
        rs_lo += __shfl_xor_sync(0xffffffff, rs_lo, 1);
        rs_lo += __shfl_xor_sync(0xffffffff, rs_lo, 2);
        rs_hi += __shfl_xor_sync(0xffffffff, rs_hi, 1);
        rs_hi += __shfl_xor_sync(0xffffffff, rs_hi, 2);

        float al_lo = __expf(m_lo - mn_lo);
        float al_hi = __expf(m_hi - mn_hi);
        l_lo = l_lo * al_lo + rs_lo;
        l_hi = l_hi * al_hi + rs_hi;
        m_lo = mn_lo; m_hi = mn_hi;
#pragma unroll
        for (int nt = 0; nt < 16; nt++) {
            O[nt][0] *= al_lo; O[nt][1] *= al_lo;
            O[nt][2] *= al_hi; O[nt][3] *= al_hi;
        }

#pragma unroll
        for (int ks = 0; ks < 8; ks++) {
            uint32_t af[4];
            af[0] = h2bits(__floats2half2_rn(S[2 * ks][0],     S[2 * ks][1]));
            af[1] = h2bits(__floats2half2_rn(S[2 * ks][2],     S[2 * ks][3]));
            af[2] = h2bits(__floats2half2_rn(S[2 * ks + 1][0], S[2 * ks + 1][1]));
            af[3] = h2bits(__floats2half2_rn(S[2 * ks + 1][2], S[2 * ks + 1][3]));
#pragma unroll
            for (int p = 0; p < 8; p++) {
                uint32_t r[4];
                ldsm_x4_t(r, vFrag + vOff + ks * (16 * FSTR * 2) + p * 32);
                mma_f16(O[2 * p], af, r);
                mma_f16(O[2 * p + 1], af, r + 2);
            }
        }
    }

    const float inv_lo = 1.0f / l_lo, inv_hi = 1.0f / l_hi;
    const int m0 = qb * 128 + w * 16 + lr;
#pragma unroll
    for (int nt = 0; nt < 16; nt++) {
        int d = nt * 8 + lc * 2;
        __half2 v0 = __floats2half2_rn(O[nt][0] * inv_lo, O[nt][1] * inv_lo);
        __half2 v1 = __floats2half2_rn(O[nt][2] * inv_hi, O[nt][3] * inv_hi);
        *(__half2*)&attn_out[(((size_t)b * SS + m0) * HH + h) * DD + d] = v0;
        *(__half2*)&attn_out[(((size_t)b * SS + m0 + 8) * HH + h) * DD + d] = v1;
    }
}

// ---------------- launch ----------------------------------------------------
extern "C" void kernel_launch(void* const* d_in, const int* in_sizes, int n_in,
                              void* d_out, int out_size) {
    const float* x      = (const float*)d_in[0];
    const float* f_r    = (const float*)d_in[1];
    const float* f_i    = (const float*)d_in[2];
    const float* mask   = (const float*)d_in[3];
    const float* W_qkv  = (const float*)d_in[4];
    const float* b_qkv  = (const float*)d_in[5];
    const float* W_o    = (const float*)d_in[6];

    float* out   = (float*)d_out;
    float* out_k = out   + (size_t)BB * SS * NSTATE;
    float* out_v = out_k + (size_t)BB * SS * HH * DD;

    __half* attnh = nullptr; cudaGetSymbolAddress((void**)&attnh, g_attnh);
    __half* xh = nullptr;    cudaGetSymbolAddress((void**)&xh,    g_xh);
    __half* wqh = nullptr;   cudaGetSymbolAddress((void**)&wqh,   g_wqh);
    __half* woh = nullptr;   cudaGetSymbolAddress((void**)&woh,   g_woh);
    __half* qh = nullptr;    cudaGetSymbolAddress((void**)&qh,    g_qh);
    __half* kh = nullptr;    cudaGetSymbolAddress((void**)&kh,    g_kh);
    __half* vh = nullptr;    cudaGetSymbolAddress((void**)&vh,    g_vh);

    const int M = BB * SS;   // 4096

    cudaFuncSetAttribute(gemm_mma, cudaFuncAttributeMaxDynamicSharedMemorySize,
                         G_SMEM);
    cudaFuncSetAttribute(gemm_qkv_rope,
                         cudaFuncAttributeMaxDynamicSharedMemorySize, G_SMEM);
    cudaFuncSetAttribute(flash_attn, cudaFuncAttributeMaxDynamicSharedMemorySize,
                         FA_BYTES);

    // 0) pre-round GEMM inputs to fp16
    {
        int n4x = (M * NSTATE) / 4;
        round_half<<<(n4x + 255) / 256, 256>>>(x, xh, n4x);
        int n4q = (QKV_W * NSTATE) / 4;
        round_half<<<(n4q + 255) / 256, 256>>>(W_qkv, wqh, n4q);
        int n4o = (NSTATE * NSTATE) / 4;
        round_half<<<(n4o + 255) / 256, 256>>>(W_o, woh, n4o);
    }

    // 1) QKV projection with fused bias + RoPE + scatter epilogue
    gemm_qkv_rope<<<dim3(QKV_W / 128, M / 128), 128, G_SMEM>>>(
        xh, wqh, b_qkv, f_r, f_i, out_k, out_v, qh, kh, vh);
    // 2) attention (fp16 mma, trans-ldmatrix V, register P, cp.async)
    flash_attn<<<dim3(SS / 128, HH, BB), 256, FA_BYTES>>>(qh, kh, vh,
                                                          mask, attnh);
    // 3) output projection
    gemm_mma<<<dim3(NSTATE / 128, M / 128), 128, G_SMEM>>>(
        attnh, woh, out, M, NSTATE, NSTATE);
}

// round 15
// speedup vs baseline: 1.0338x; 1.0338x over previous
#include <cuda_runtime.h>
#include <cuda_fp16.h>
#include <cstdint>
#include <math.h>

// Problem constants
#define BB 2
#define SS 2048
#define HH 16
#define DD 128
#define NSTATE 2048
#define QKV_W (3*HH*DD)   // 6144

// ---------------- scratch (device globals; no runtime alloc) ----------------
__device__ float  g_qkv[(size_t)BB * SS * QKV_W];     // [B,S,6144] fp32
__device__ __half g_attnh[(size_t)BB * SS * HH * DD]; // attn out, half
__device__ __half g_xh[(size_t)BB * SS * NSTATE];     // x half
__device__ __half g_wqh[(size_t)QKV_W * NSTATE];      // W_qkv half
__device__ __half g_woh[(size_t)NSTATE * NSTATE];     // W_o half
__device__ __half g_qh[(size_t)BB * HH * SS * DD];    // q half prescaled [B,H,S,D]
__device__ __half g_kh[(size_t)BB * HH * SS * DD];    // k half [B,H,S,D]
__device__ __half g_vh[(size_t)BB * HH * SS * DD];    // v half [B,H,S,D]

// ---------------- helpers ----------------------------------------------------
__device__ __forceinline__ uint32_t smem_u32(const void* p) {
    uint32_t a;
    asm("{ .reg .u64 t; cvta.to.shared.u64 t, %1; cvt.u32.u64 %0, t; }"
        : "=r"(a) : "l"(p));
    return a;
}
__device__ __forceinline__ void mma_f16(float* c, const uint32_t* a,
                                        const uint32_t* b) {
    asm volatile(
        "mma.sync.aligned.m16n8k16.row.col.f32.f16.f16.f32 "
        "{%0,%1,%2,%3}, {%4,%5,%6,%7}, {%8,%9}, {%0,%1,%2,%3};\n"
        : "+f"(c[0]), "+f"(c[1]), "+f"(c[2]), "+f"(c[3])
        : "r"(a[0]), "r"(a[1]), "r"(a[2]), "r"(a[3]), "r"(b[0]), "r"(b[1]));
}
__device__ __forceinline__ void ldsm_x4(uint32_t* r, uint32_t addr) {
    asm volatile("ldmatrix.sync.aligned.m8n8.x4.shared.b16 {%0,%1,%2,%3}, [%4];"
                 : "=r"(r[0]), "=r"(r[1]), "=r"(r[2]), "=r"(r[3]) : "r"(addr));
}
__device__ __forceinline__ void ldsm_x4_t(uint32_t* r, uint32_t addr) {
    asm volatile("ldmatrix.sync.aligned.m8n8.x4.trans.shared.b16 {%0,%1,%2,%3}, [%4];"
                 : "=r"(r[0]), "=r"(r[1]), "=r"(r[2]), "=r"(r[3]) : "r"(addr));
}
__device__ __forceinline__ void cp16(uint32_t s, const void* g) {
    asm volatile("cp.async.cg.shared.global [%0], [%1], 16;"
                 :: "r"(s), "l"(g) : "memory");
}
__device__ __forceinline__ uint32_t h2bits(__half2 h) {
    return *(uint32_t*)&h;
}
#define CP_COMMIT() asm volatile("cp.async.commit_group;" ::: "memory")
#define CP_WAIT1()  asm volatile("cp.async.wait_group 1;"  ::: "memory")
#define CP_WAIT0()  asm volatile("cp.async.wait_group 0;"  ::: "memory")

// ---------------- fp32 -> fp16 pre-round pass --------------------------------
__global__ void round_half(const float* __restrict__ src,
                           __half* __restrict__ dst, int n4) {
    int i = blockIdx.x * blockDim.x + threadIdx.x;
    if (i >= n4) return;
    float4 v = ((const float4*)src)[i];
    __half2 h0 = __floats2half2_rn(v.x, v.y);
    __half2 h1 = __floats2half2_rn(v.z, v.w);
    uint2 o = { *(uint32_t*)&h0, *(uint32_t*)&h1 };
    ((uint2*)dst)[i] = o;
}

// ============================================================================
// fp16 mma.sync GEMM (NT): C[m,n] = sum_k A[m,k]*B[n,k] (+bias[n]), fp32 acc
// Block 128x128, BK=32 halves, 4 warps (2x2), warp tile 64x64.
// 5-stage cp.async ring, TWO chunks per barrier (halved sync overhead).
// TPH=40 rows, ldmatrix. 2 CTAs/SM (128 thr each).
// ============================================================================
#define TPH 40                                // halves; 80B row (5x16B, odd)
#define G_NSTG 5
#define G_AB (128 * TPH * 2)                  // 10240 B per operand tile
#define G_STG (2 * G_AB)                      // 20480 B per stage
#define G_SMEM (G_NSTG * G_STG)               // 102400 B

__device__ __forceinline__ void gemm_issue(uint32_t sbase,
                                           const __half* __restrict__ A,
                                           const __half* __restrict__ B,
                                           int m0, int n0, int K, int k0,
                                           int tid) {
#pragma unroll
    for (int j = 0; j < 4; j++) {               // 512 chunks of A
        int t = tid + j * 128;
        int row = t >> 2, seg = t & 3;
        cp16(sbase + (uint32_t)(row * TPH + seg * 8) * 2,
             &A[(size_t)(m0 + row) * K + k0 + seg * 8]);
    }
    const uint32_t sB = sbase + G_AB;
#pragma unroll
    for (int j = 0; j < 4; j++) {               // 512 chunks of B
        int t = tid + j * 128;
        int row = t >> 2, seg = t & 3;
        cp16(sB + (uint32_t)(row * TPH + seg * 8) * 2,
             &B[(size_t)(n0 + row) * K + k0 + seg * 8]);
    }
}

__global__ __launch_bounds__(128, 2)
void gemm_mma(const __half* __restrict__ A, const __half* __restrict__ B,
              const float* __restrict__ bias, float* __restrict__ C,
              int M, int N, int K) {
    extern __shared__ uint32_t dynsm[];
    const uint32_t sb = smem_u32(dynsm);

    const int tid = threadIdx.x;
    const int w = tid >> 5, l = tid & 31;
    const int lr = l >> 2, lc = l & 3;
    const int wm = w >> 1, wn = w & 1;           // 2 (m) x 2 (n)
    const int m0 = blockIdx.y * 128, n0 = blockIdx.x * 128;
    const int mat = l >> 3;

    const uint32_t aOff = (uint32_t)(((wm * 64 + (mat & 1) * 8 + (l & 7)) * TPH)
                                     + (mat >> 1) * 8) * 2;
    const uint32_t bOff = G_AB
                        + (uint32_t)(((wn * 64 + (mat >> 1) * 8 + (l & 7)) * TPH)
                                     + (mat & 1) * 8) * 2;

    float acc[4][8][4];
#pragma unroll
    for (int mt = 0; mt < 4; mt++)
#pragma unroll
        for (int nt = 0; nt < 8; nt++)
#pragma unroll
            for (int i = 0; i < 4; i++) acc[mt][nt][i] = 0.f;

    const int NC = K / 32;                       // even (K=2048 -> 64)

    // prologue: stages 0..2
#pragma unroll
    for (int s = 0; s < 3; s++) {
        gemm_issue(sb + s * G_STG, A, B, m0, n0, K, s * 32, tid);
        CP_COMMIT();
    }

    for (int c = 0; c < NC; c += 2) {
        CP_WAIT1();            // stages c, c+1 resident
        __syncthreads();

        // issue stages c+3, c+4 (ring slots (c+3)%5, (c+4)%5 are retired)
#pragma unroll
        for (int j = 3; j <= 4; j++) {
            int nc = c + j;
            if (nc < NC)
                gemm_issue(sb + (nc % G_NSTG) * G_STG, A, B, m0, n0, K,
                           nc * 32, tid);
            CP_COMMIT();
        }

        // compute chunks c and c+1
#pragma unroll
        for (int cc = 0; cc < 2; cc++) {
            const uint32_t st = sb + ((c + cc) % G_NSTG) * G_STG;
#pragma unroll
            for (int kk = 0; kk < 2; kk++) {
                uint32_t af[4][4];
#pragma unroll
                for (int mt = 0; mt < 4; mt++)
                    ldsm_x4(af[mt], st + aOff + kk * 32 + mt * (16 * TPH * 2));
#pragma unroll
                for (int p = 0; p < 4; p++) {
                    uint32_t r[4];
                    ldsm_x4(r, st + bOff + kk * 32 + p * (16 * TPH * 2));
#pragma unroll
                    for (int mt = 0; mt < 4; mt++) {
                        mma_f16(acc[mt][2 * p],     af[mt], r);
                        mma_f16(acc[mt][2 * p + 1], af[mt], r + 2);
                    }
                }
            }
        }
    }

#pragma unroll
    for (int mt = 0; mt < 4; mt++) {
        int m = m0 + wm * 64 + mt * 16 + lr;
#pragma unroll
        for (int nt = 0; nt < 8; nt++) {
            int n = n0 + wn * 64 + nt * 8 + lc * 2;
            float bx = 0.f, by = 0.f;
            if (bias) { bx = bias[n]; by = bias[n + 1]; }
            float2 v0 = { acc[mt][nt][0] + bx, acc[mt][nt][1] + by };
            float2 v1 = { acc[mt][nt][2] + bx, acc[mt][nt][3] + by };
            *(float2*)&C[(size_t)m * N + n] = v0;
            *(float2*)&C[(size_t)(m + 8) * N + n] = v1;
        }
    }
}

// ---------------- RoPE: q -> g_qh (half, prescaled, head-major);
//                  k -> out_k (fp32) + g_kh; v -> out_v (fp32) + g_vh --------
__global__ void rope_scatter(const float* __restrict__ qkv,
                             const float* __restrict__ f_r,
                             const float* __restrict__ f_i,
                             float* __restrict__ out_k,
                             float* __restrict__ out_v,
                             __half* __restrict__ qh,
                             __half* __restrict__ kh,
                             __half* __restrict__ vh) {
    int idx = blockIdx.x * blockDim.x + threadIdx.x;
    if (idx >= BB * SS * HH * 64) return;
    int d2 = idx & 63;
    int h  = (idx >> 6) & (HH - 1);
    int bs = idx >> 10;
    int b = bs >> 11, s = bs & (SS - 1);
    const float scale = 0.08838834764831845f;   // 1/sqrt(128)

    float fr = f_r[(size_t)bs * 64 + d2];
    float fi = f_i[(size_t)bs * 64 + d2];

    size_t base = (size_t)bs * QKV_W;
    size_t hmaj = (((size_t)(b * HH + h) * SS) + s) * DD + d2;

    size_t qi = base + (size_t)h * DD + d2;
    float xr = qkv[qi], xi = qkv[qi + 64];
    qh[hmaj]      = __float2half_rn((xr * fr - xi * fi) * scale);
    qh[hmaj + 64] = __float2half_rn((xr * fi + xi * fr) * scale);

    size_t ki = base + (size_t)HH * DD + (size_t)h * DD + d2;
    xr = qkv[ki]; xi = qkv[ki + 64];
    float klo = xr * fr - xi * fi;
    float khi = xr * fi + xi * fr;
    size_t ko = ((size_t)bs * HH + h) * DD + d2;
    out_k[ko]      = klo;
    out_k[ko + 64] = khi;
    kh[hmaj]      = __float2half_rn(klo);
    kh[hmaj + 64] = __float2half_rn(khi);

    size_t vi = base + (size_t)2 * HH * DD + (size_t)h * DD + d2;
    float vlo = qkv[vi], vhi = qkv[vi + 64];
    out_v[ko]      = vlo;
    out_v[ko + 64] = vhi;
    vh[hmaj]      = __float2half_rn(vlo);
    vh[hmaj + 64] = __float2half_rn(vhi);
}

// ============================================================================
// Flash attention, fp16 mma.sync + ldmatrix(+trans for V) + cp.async.
// BM=128 (8 warps x 16), BN=128. Q/K/V all half head-major [B,H,S,D].
// Q fragments hoisted; P register-resident. Causal; heavy tiles first.
// ============================================================================
#define FSTR 136   // halves: row stride (272B, odd 16B count)
#define FA_KB   (128 * FSTR)             // K stage, halves
#define FA_VB   (128 * FSTR)             // V stage, halves
#define FA_BYTES ((128*FSTR /*Q*/ + 2*FA_KB + 2*FA_VB) * 2)   // 174080 B

__global__ __launch_bounds__(256, 1)
void flash_attn(const __half* __restrict__ qh,
                const __half* __restrict__ kh,
                const __half* __restrict__ vh,
                const float* __restrict__ mask,
                __half* __restrict__ attn_out) {
    extern __shared__ __half smh[];
    __half* Qs  = smh;                    // [128][FSTR]
    __half* Ks0 = Qs + 128 * FSTR;        // [2][128][FSTR]  rows = kv pos
    __half* Vs0 = Ks0 + 2 * FA_KB;        // [2][128][FSTR]  rows = kv pos

    const int qb = (int)gridDim.x - 1 - (int)blockIdx.x;
    const int h = blockIdx.y, b = blockIdx.z;
    const int tid = threadIdx.x, w = tid >> 5, l = tid & 31;
    const int lr = l >> 2, lc = l & 3;

    const int mat = l >> 3;
    const uint32_t sQ = smem_u32(Qs), sK = smem_u32(Ks0);
    const uint32_t sV = smem_u32(Vs0);
    const uint32_t qFrag = sQ + (uint32_t)(((w * 16 + (mat & 1) * 8 + (l & 7)) * FSTR)
                                           + (mat >> 1) * 8) * 2;
    const uint32_t kFrag = sK + (uint32_t)((((mat >> 1) * 8 + (l & 7)) * FSTR)
                                           + (mat & 1) * 8) * 2;
    const uint32_t vFrag = sV + (uint32_t)((((mat & 1) * 8 + (l & 7)) * FSTR)
                                           + (mat >> 1) * 8) * 2;

    const __half* qrh = qh + ((size_t)(b * HH + h) * SS) * DD;
    const __half* krh = kh + ((size_t)(b * HH + h) * SS) * DD;
    const __half* vrh = vh + ((size_t)(b * HH + h) * SS) * DD;

    auto issue_kv = [&](int buf, int kb) {
        const uint32_t kBase = sK + (uint32_t)buf * (FA_KB * 2);
        const uint32_t vBase = sV + (uint32_t)buf * (FA_VB * 2);
#pragma unroll
        for (int j = 0; j < 8; j++) {
            int t = tid + j * 256;
            int r = t >> 4, c8 = t & 15;
            cp16(kBase + (uint32_t)(r * FSTR + c8 * 8) * 2,
                 &krh[(size_t)(kb * 128 + r) * DD + c8 * 8]);
        }
#pragma unroll
        for (int j = 0; j < 8; j++) {
            int t = tid + j * 256;
            int r = t >> 4, c8 = t & 15;
            cp16(vBase + (uint32_t)(r * FSTR + c8 * 8) * 2,
                 &vrh[(size_t)(kb * 128 + r) * DD + c8 * 8]);
        }
    };

#pragma unroll
    for (int j = 0; j < 8; j++) {
        int t = tid + j * 256;
        int r = t >> 4, c8 = t & 15;
        cp16(sQ + (uint32_t)(r * FSTR + c8 * 8) * 2,
             &qrh[(size_t)(qb * 128 + r) * DD + c8 * 8]);
    }
    CP_COMMIT();
    issue_kv(0, 0);
    CP_COMMIT();
    CP_WAIT0();
    __syncthreads();

    uint32_t qf[8][4];
#pragma unroll
    for (int ks = 0; ks < 8; ks++)
        ldsm_x4(qf[ks], qFrag + ks * 32);

    float O[16][4];
#pragma unroll
    for (int nt = 0; nt < 16; nt++)
#pragma unroll
        for (int i = 0; i < 4; i++) O[nt][i] = 0.f;
    float m_lo = -INFINITY, m_hi = -INFINITY, l_lo = 0.f, l_hi = 0.f;

    const int nKV = qb + 1;

    for (int kb = 0; kb < nKV; kb++) {
        const int buf = kb & 1;
        if (kb > 0) {
            CP_WAIT0();
            __syncthreads();
        }
        if (kb + 1 < nKV) {
            issue_kv(buf ^ 1, kb + 1);
            CP_COMMIT();
        }

        const uint32_t kOff = (uint32_t)buf * (FA_KB * 2);
        const uint32_t vOff = (uint32_t)buf * (FA_VB * 2);

        float S[16][4];
#pragma unroll
        for (int nt = 0; nt < 16; nt++)
#pragma unroll
            for (int i = 0; i < 4; i++) S[nt][i] = 0.f;
#pragma unroll
        for (int ks = 0; ks < 8; ks++) {
#pragma unroll
            for (int p = 0; p < 8; p++) {
                uint32_t r[4];
                ldsm_x4(r, kFrag + kOff + ks * 32 + p * (16 * FSTR * 2));
                mma_f16(S[2 * p], qf[ks], r);
                mma_f16(S[2 * p + 1], qf[ks], r + 2);
            }
        }

        if (kb == qb) {
            const int m_glo = qb * 128 + w * 16 + lr;
            const float* mr0 = &mask[((size_t)b * SS + m_glo) * SS + kb * 128];
            const float* mr1 = mr0 + 8 * SS;
#pragma unroll
            for (int nt = 0; nt < 16; nt++) {
                float2 q0 = *(const float2*)&mr0[nt * 8 + lc * 2];
                float2 q1 = *(const float2*)&mr1[nt * 8 + lc * 2];
                S[nt][0] += q0.x; S[nt][1] += q0.y;
                S[nt][2] += q1.x; S[nt][3] += q1.y;
            }
        }

        float bm_lo = -INFINITY, bm_hi = -INFINITY;
#pragma unroll
        for (int nt = 0; nt < 16; nt++) {
            bm_lo = fmaxf(bm_lo, fmaxf(S[nt][0], S[nt][1]));
            bm_hi = fmaxf(bm_hi, fmaxf(S[nt][2], S[nt][3]));
        }
        bm_lo = fmaxf(bm_lo, __shfl_xor_sync(0xffffffff, bm_lo, 1));
        bm_lo = fmaxf(bm_lo, __shfl_xor_sync(0xffffffff, bm_lo, 2));
        bm_hi = fmaxf(bm_hi, __shfl_xor_sync(0xffffffff, bm_hi, 1));
        bm_hi = fmaxf(bm_hi, __shfl_xor_sync(0xffffffff, bm_hi, 2));
        float mn_lo = fmaxf(m_lo, bm_lo);
        float mn_hi = fmaxf(m_hi, bm_hi);

        float rs_lo = 0.f, rs_hi = 0.f;
#pragma unroll
        for (int nt = 0; nt < 16; nt++) {
            S[nt][0] = __expf(S[nt][0] - mn_lo);
            S[nt][1] = __expf(S[nt][1] - mn_lo);
            S[nt][2] = __expf(S[nt][2] - mn_hi);
            S[nt][3] = __expf(S[nt][3] - mn_hi);
            rs_lo += S[nt][0] + S[nt][1];
            rs_hi += S[nt][2] + S[nt][3];
        }
        rs_lo += __shfl_xor_sync(0xffffffff, rs_lo, 1);
        rs_lo += __shfl_xor_sync(0xffffffff, rs_lo, 2);
        rs_hi += __shfl_xor_sync(0xffffffff, rs_hi, 1);
        rs_hi += __shfl_xor_sync(0xffffffff, rs_hi, 2);

        float al_lo = __expf(m_lo - mn_lo);
        float al_hi = __expf(m_hi - mn_hi);
        l_lo = l_lo * al_lo + rs_lo;
        l_hi = l_hi * al_hi + rs_hi;
        m_lo = mn_lo; m_hi = mn_hi;
#pragma unroll
        for (int nt = 0; nt < 16; nt++) {
            O[nt][0] *= al_lo; O[nt][1] *= al_lo;
            O[nt][2] *= al_hi; O[nt][3] *= al_hi;
        }

#pragma unroll
        for (int ks = 0; ks < 8; ks++) {
            uint32_t af[4];
            af[0] = h2bits(__floats2half2_rn(S[2 * ks][0],     S[2 * ks][1]));
            af[1] = h2bits(__floats2half2_rn(S[2 * ks][2],     S[2 * ks][3]));
            af[2] = h2bits(__floats2half2_rn(S[2 * ks + 1][0], S[2 * ks + 1][1]));
            af[3] = h2bits(__floats2half2_rn(S[2 * ks + 1][2], S[2 * ks + 1][3]));
#pragma unroll
            for (int p = 0; p < 8; p++) {
                uint32_t r[4];
                ldsm_x4_t(r, vFrag + vOff + ks * (16 * FSTR * 2) + p * 32);
                mma_f16(O[2 * p], af, r);
                mma_f16(O[2 * p + 1], af, r + 2);
            }
        }
    }

    const float inv_lo = 1.0f / l_lo, inv_hi = 1.0f / l_hi;
    const int m0 = qb * 128 + w * 16 + lr;
#pragma unroll
    for (int nt = 0; nt < 16; nt++) {
        int d = nt * 8 + lc * 2;
        __half2 v0 = __floats2half2_rn(O[nt][0] * inv_lo, O[nt][1] * inv_lo);
        __half2 v1 = __floats2half2_rn(O[nt][2] * inv_hi, O[nt][3] * inv_hi);
        *(__half2*)&attn_out[(((size_t)b * SS + m0) * HH + h) * DD + d] = v0;
        *(__half2*)&attn_out[(((size_t)b * SS + m0 + 8) * HH + h) * DD + d] = v1;
    }
}

// ---------------- launch ----------------------------------------------------
extern "C" void kernel_launch(void* const* d_in, const int* in_sizes, int n_in,
                              void* d_out, int out_size) {
    const float* x      = (const float*)d_in[0];
    const float* f_r    = (const float*)d_in[1];
    const float* f_i    = (const float*)d_in[2];
    const float* mask   = (const float*)d_in[3];
    const float* W_qkv  = (const float*)d_in[4];
    const float* b_qkv  = (const float*)d_in[5];
    const float* W_o    = (const float*)d_in[6];

    float* out   = (float*)d_out;
    float* out_k = out   + (size_t)BB * SS * NSTATE;
    float* out_v = out_k + (size_t)BB * SS * HH * DD;

    float* qkv = nullptr;    cudaGetSymbolAddress((void**)&qkv,   g_qkv);
    __half* attnh = nullptr; cudaGetSymbolAddress((void**)&attnh, g_attnh);
    __half* xh = nullptr;    cudaGetSymbolAddress((void**)&xh,    g_xh);
    __half* wqh = nullptr;   cudaGetSymbolAddress((void**)&wqh,   g_wqh);
    __half* woh = nullptr;   cudaGetSymbolAddress((void**)&woh,   g_woh);
    __half* qh = nullptr;    cudaGetSymbolAddress((void**)&qh,    g_qh);
    __half* kh = nullptr;    cudaGetSymbolAddress((void**)&kh,    g_kh);
    __half* vh = nullptr;    cudaGetSymbolAddress((void**)&vh,    g_vh);

    const int M = BB * SS;   // 4096

    cudaFuncSetAttribute(gemm_mma, cudaFuncAttributeMaxDynamicSharedMemorySize,
                         G_SMEM);
    cudaFuncSetAttribute(flash_attn, cudaFuncAttributeMaxDynamicSharedMemorySize,
                         FA_BYTES);

    // 0) pre-round GEMM inputs to fp16
    {
        int n4x = (M * NSTATE) / 4;
        round_half<<<(n4x + 255) / 256, 256>>>(x, xh, n4x);
        int n4q = (QKV_W * NSTATE) / 4;
        round_half<<<(n4q + 255) / 256, 256>>>(W_qkv, wqh, n4q);
        int n4o = (NSTATE * NSTATE) / 4;
        round_half<<<(n4o + 255) / 256, 256>>>(W_o, woh, n4o);
    }

    // 1) QKV projection (fp16 mma.sync, 2-chunk pipelined)
    gemm_mma<<<dim3(QKV_W / 128, M / 128), 128, G_SMEM>>>(
        xh, wqh, b_qkv, qkv, M, QKV_W, NSTATE);
    // 2) RoPE: q/k/v -> half head-major + fp32 k,v outputs
    rope_scatter<<<(BB * SS * HH * 64) / 256, 256>>>(qkv, f_r, f_i,
                                                     out_k, out_v, qh, kh, vh);
    // 3) attention (fp16 mma, trans-ldmatrix V, register P, cp.async)
    flash_attn<<<dim3(SS / 128, HH, BB), 256, FA_BYTES>>>(qh, kh, vh,
                                                          mask, attnh);
    // 4) output projection (fp16 mma.sync, 2-chunk pipelined)
    gemm_mma<<<dim3(NSTATE / 128, M / 128), 128, G_SMEM>>>(
        attnh, woh, nullptr, out, M, NSTATE, NSTATE);
}

// round 16
// speedup vs baseline: 1.1316x; 1.0947x over previous
#include <cuda_runtime.h>
#include <cuda_fp16.h>
#include <cstdint>
#include <math.h>

// Problem constants
#define BB 2
#define SS 2048
#define HH 16
#define DD 128
#define NSTATE 2048
#define QKV_W (3*HH*DD)   // 6144

// ---------------- scratch (device globals; no runtime alloc) ----------------
__device__ __half g_attnh[(size_t)BB * SS * HH * DD]; // attn out, half
__device__ __half g_xh[(size_t)BB * SS * NSTATE];     // x half
__device__ __half g_wqh[(size_t)QKV_W * NSTATE];      // W_qkv half
__device__ __half g_woh[(size_t)NSTATE * NSTATE];     // W_o half
__device__ __half g_qh[(size_t)BB * HH * SS * DD];    // q half prescaled [B,H,S,D]
__device__ __half g_kh[(size_t)BB * HH * SS * DD];    // k half [B,H,S,D]
__device__ __half g_vh[(size_t)BB * HH * SS * DD];    // v half [B,H,S,D]

// ---------------- helpers ----------------------------------------------------
__device__ __forceinline__ uint32_t smem_u32(const void* p) {
    uint32_t a;
    asm("{ .reg .u64 t; cvta.to.shared.u64 t, %1; cvt.u32.u64 %0, t; }"
        : "=r"(a) : "l"(p));
    return a;
}
__device__ __forceinline__ void mma_f16(float* c, const uint32_t* a,
                                        const uint32_t* b) {
    asm volatile(
        "mma.sync.aligned.m16n8k16.row.col.f32.f16.f16.f32 "
        "{%0,%1,%2,%3}, {%4,%5,%6,%7}, {%8,%9}, {%0,%1,%2,%3};\n"
        : "+f"(c[0]), "+f"(c[1]), "+f"(c[2]), "+f"(c[3])
        : "r"(a[0]), "r"(a[1]), "r"(a[2]), "r"(a[3]), "r"(b[0]), "r"(b[1]));
}
__device__ __forceinline__ void ldsm_x4(uint32_t* r, uint32_t addr) {
    asm volatile("ldmatrix.sync.aligned.m8n8.x4.shared.b16 {%0,%1,%2,%3}, [%4];"
                 : "=r"(r[0]), "=r"(r[1]), "=r"(r[2]), "=r"(r[3]) : "r"(addr));
}
__device__ __forceinline__ void ldsm_x4_t(uint32_t* r, uint32_t addr) {
    asm volatile("ldmatrix.sync.aligned.m8n8.x4.trans.shared.b16 {%0,%1,%2,%3}, [%4];"
                 : "=r"(r[0]), "=r"(r[1]), "=r"(r[2]), "=r"(r[3]) : "r"(addr));
}
__device__ __forceinline__ void cp16(uint32_t s, const void* g) {
    asm volatile("cp.async.cg.shared.global [%0], [%1], 16;"
                 :: "r"(s), "l"(g) : "memory");
}
__device__ __forceinline__ uint32_t h2bits(__half2 h) {
    return *(uint32_t*)&h;
}
#define CP_COMMIT() asm volatile("cp.async.commit_group;" ::: "memory")
#define CP_WAIT2()  asm volatile("cp.async.wait_group 2;"  ::: "memory")
#define CP_WAIT0()  asm volatile("cp.async.wait_group 0;"  ::: "memory")

// ---------------- fp32 -> fp16 pre-round pass --------------------------------
__global__ void round_half(const float* __restrict__ src,
                           __half* __restrict__ dst, int n4) {
    int i = blockIdx.x * blockDim.x + threadIdx.x;
    if (i >= n4) return;
    float4 v = ((const float4*)src)[i];
    __half2 h0 = __floats2half2_rn(v.x, v.y);
    __half2 h1 = __floats2half2_rn(v.z, v.w);
    uint2 o = { *(uint32_t*)&h0, *(uint32_t*)&h1 };
    ((uint2*)dst)[i] = o;
}

// ============================================================================
// Shared GEMM config: block 128x128, BK=32 halves, 4 warps (2x2), 64x64 warp
// tiles, 4-stage cp.async ring (round-13 proven config), TPH=40. 2 CTAs/SM.
// ============================================================================
#define TPH 40                                // halves; 80B row (5x16B, odd)
#define G_NSTG 4
#define G_AB (128 * TPH * 2)                  // 10240 B per operand tile
#define G_STG (2 * G_AB)                      // 20480 B per stage
#define G_SMEM (G_NSTG * G_STG)               // 81920 B

__device__ __forceinline__ void gemm_issue(uint32_t sbase,
                                           const __half* __restrict__ A,
                                           const __half* __restrict__ B,
                                           int m0, int n0, int K, int k0,
                                           int tid) {
#pragma unroll
    for (int j = 0; j < 4; j++) {               // 512 chunks of A
        int t = tid + j * 128;
        int row = t >> 2, seg = t & 3;
        cp16(sbase + (uint32_t)(row * TPH + seg * 8) * 2,
             &A[(size_t)(m0 + row) * K + k0 + seg * 8]);
    }
    const uint32_t sB = sbase + G_AB;
#pragma unroll
    for (int j = 0; j < 4; j++) {               // 512 chunks of B
        int t = tid + j * 128;
        int row = t >> 2, seg = t & 3;
        cp16(sB + (uint32_t)(row * TPH + seg * 8) * 2,
             &B[(size_t)(n0 + row) * K + k0 + seg * 8]);
    }
}

// Round-13 mainloop (acc[4][8][4] in caller's registers)
#define GEMM_MAINLOOP(A, B, m0, n0, K)                                        \
    const int NC = (K) / 32;                                                  \
    _Pragma("unroll")                                                         \
    for (int s = 0; s < G_NSTG - 1; s++) {                                    \
        gemm_issue(sb + s * G_STG, A, B, m0, n0, K, s * 32, tid);             \
        CP_COMMIT();                                                          \
    }                                                                         \
    for (int c = 0; c < NC; c++) {                                            \
        CP_WAIT2();                                                           \
        __syncthreads();                                                      \
        const int nc = c + G_NSTG - 1;                                        \
        if (nc < NC)                                                          \
            gemm_issue(sb + (nc % G_NSTG) * G_STG, A, B, m0, n0, K,           \
                       nc * 32, tid);                                         \
        CP_COMMIT();                                                          \
        const uint32_t st = sb + (c % G_NSTG) * G_STG;                        \
        _Pragma("unroll")                                                     \
        for (int kk = 0; kk < 2; kk++) {                                      \
            uint32_t af[4][4];                                                \
            _Pragma("unroll")                                                 \
            for (int mt = 0; mt < 4; mt++)                                    \
                ldsm_x4(af[mt], st + aOff + kk * 32 + mt * (16 * TPH * 2));   \
            _Pragma("unroll")                                                 \
            for (int p = 0; p < 4; p++) {                                     \
                uint32_t r[4];                                                \
                ldsm_x4(r, st + bOff + kk * 32 + p * (16 * TPH * 2));         \
                _Pragma("unroll")                                             \
                for (int mt = 0; mt < 4; mt++) {                              \
                    mma_f16(acc[mt][2 * p],     af[mt], r);                   \
                    mma_f16(acc[mt][2 * p + 1], af[mt], r + 2);               \
                }                                                             \
            }                                                                 \
        }                                                                     \
    }

// ============================================================================
// Output-projection GEMM (NT): C fp32 = A @ B^T
// ============================================================================
__global__ __launch_bounds__(128, 2)
void gemm_mma(const __half* __restrict__ A, const __half* __restrict__ B,
              float* __restrict__ C, int M, int N, int K) {
    extern __shared__ uint32_t dynsm[];
    const uint32_t sb = smem_u32(dynsm);

    const int tid = threadIdx.x;
    const int w = tid >> 5, l = tid & 31;
    const int lr = l >> 2, lc = l & 3;
    const int wm = w >> 1, wn = w & 1;
    const int m0 = blockIdx.y * 128, n0 = blockIdx.x * 128;
    const int mat = l >> 3;

    const uint32_t aOff = (uint32_t)(((wm * 64 + (mat & 1) * 8 + (l & 7)) * TPH)
                                     + (mat >> 1) * 8) * 2;
    const uint32_t bOff = G_AB
                        + (uint32_t)(((wn * 64 + (mat >> 1) * 8 + (l & 7)) * TPH)
                                     + (mat & 1) * 8) * 2;

    float acc[4][8][4];
#pragma unroll
    for (int mt = 0; mt < 4; mt++)
#pragma unroll
        for (int nt = 0; nt < 8; nt++)
#pragma unroll
            for (int i = 0; i < 4; i++) acc[mt][nt][i] = 0.f;

    GEMM_MAINLOOP(A, B, m0, n0, K)

#pragma unroll
    for (int mt = 0; mt < 4; mt++) {
        int m = m0 + wm * 64 + mt * 16 + lr;
#pragma unroll
        for (int nt = 0; nt < 8; nt++) {
            int n = n0 + wn * 64 + nt * 8 + lc * 2;
            float2 v0 = { acc[mt][nt][0], acc[mt][nt][1] };
            float2 v1 = { acc[mt][nt][2], acc[mt][nt][3] };
            *(float2*)&C[(size_t)m * N + n] = v0;
            *(float2*)&C[(size_t)(m + 8) * N + n] = v1;
        }
    }
}

// ============================================================================
// QKV GEMM with fused bias + RoPE epilogue (v2: vectorized, 16 iters/thread).
// N-tile = one head of one stream: sel = bx>>4 (0=q,1=k,2=v), h = bx&15.
//   q -> g_qh (prescaled half, head-major)
//   k -> out_k fp32 [B,S,H,D] + g_kh (half, head-major)
//   v -> out_v fp32 [B,S,H,D] + g_vh (half, head-major)
// ============================================================================
#define CSTR 132   // fp32 stage row stride

__global__ __launch_bounds__(128, 2)
void gemm_qkv_rope(const __half* __restrict__ A, const __half* __restrict__ B,
                   const float* __restrict__ bias,
                   const float* __restrict__ f_r, const float* __restrict__ f_i,
                   float* __restrict__ out_k, float* __restrict__ out_v,
                   __half* __restrict__ qh, __half* __restrict__ kh,
                   __half* __restrict__ vh) {
    extern __shared__ uint32_t dynsm[];
    const uint32_t sb = smem_u32(dynsm);
    const int K = NSTATE;

    const int tid = threadIdx.x;
    const int w = tid >> 5, l = tid & 31;
    const int lr = l >> 2, lc = l & 3;
    const int wm = w >> 1, wn = w & 1;
    const int m0 = blockIdx.y * 128, n0 = blockIdx.x * 128;
    const int sel = blockIdx.x >> 4;             // 0=q, 1=k, 2=v
    const int h   = blockIdx.x & 15;
    const int mat = l >> 3;

    const uint32_t aOff = (uint32_t)(((wm * 64 + (mat & 1) * 8 + (l & 7)) * TPH)
                                     + (mat >> 1) * 8) * 2;
    const uint32_t bOff = G_AB
                        + (uint32_t)(((wn * 64 + (mat >> 1) * 8 + (l & 7)) * TPH)
                                     + (mat & 1) * 8) * 2;

    float acc[4][8][4];
#pragma unroll
    for (int mt = 0; mt < 4; mt++)
#pragma unroll
        for (int nt = 0; nt < 8; nt++)
#pragma unroll
            for (int i = 0; i < 4; i++) acc[mt][nt][i] = 0.f;

    GEMM_MAINLOOP(A, B, m0, n0, K)

    // ---- epilogue: bias, stage fp32 tile to smem ----
    __syncthreads();                  // all warps done reading last stage
    float* Ct = (float*)dynsm;        // [128][CSTR]
#pragma unroll
    for (int mt = 0; mt < 4; mt++) {
        int ml = wm * 64 + mt * 16 + lr;
#pragma unroll
        for (int nt = 0; nt < 8; nt++) {
            int nl = wn * 64 + nt * 8 + lc * 2;
            float bx = bias[n0 + nl], by = bias[n0 + nl + 1];
            Ct[ml * CSTR + nl]           = acc[mt][nt][0] + bx;
            Ct[ml * CSTR + nl + 1]       = acc[mt][nt][1] + by;
            Ct[(ml + 8) * CSTR + nl]     = acc[mt][nt][2] + bx;
            Ct[(ml + 8) * CSTR + nl + 1] = acc[mt][nt][3] + by;
        }
    }
    __syncthreads();

    // ---- rope + scatter v2: thread = (rgroup, quad); 16 float4 iterations ----
    const float scale = 0.08838834764831845f;    // 1/sqrt(128)
    const int quad = (tid & 15) * 4;             // d2 base: 0,4,...,60
    const int rg   = tid >> 4;                   // 0..7
#pragma unroll 4
    for (int i = 0; i < 16; i++) {
        int r = rg * 16 + i;
        int bs = m0 + r;
        int b = bs >> 11, s = bs & (SS - 1);
        float4 clo = *(float4*)&Ct[r * CSTR + quad];
        float4 chi = *(float4*)&Ct[r * CSTR + quad + 64];
        size_t hmaj = (((size_t)(b * HH + h) * SS) + s) * DD + quad;
        if (sel == 2) {
            size_t ko = ((size_t)bs * HH + h) * DD + quad;
            *(float4*)&out_v[ko]      = clo;
            *(float4*)&out_v[ko + 64] = chi;
            uint2 plo = { h2bits(__floats2half2_rn(clo.x, clo.y)),
                          h2bits(__floats2half2_rn(clo.z, clo.w)) };
            uint2 phi = { h2bits(__floats2half2_rn(chi.x, chi.y)),
                          h2bits(__floats2half2_rn(chi.z, chi.w)) };
            *(uint2*)&vh[hmaj]      = plo;
            *(uint2*)&vh[hmaj + 64] = phi;
        } else {
            float4 fr = *(const float4*)&f_r[(size_t)bs * 64 + quad];
            float4 fi = *(const float4*)&f_i[(size_t)bs * 64 + quad];
            float4 rlo, rhi;
            rlo.x = clo.x * fr.x - chi.x * fi.x;  rhi.x = clo.x * fi.x + chi.x * fr.x;
            rlo.y = clo.y * fr.y - chi.y * fi.y;  rhi.y = clo.y * fi.y + chi.y * fr.y;
            rlo.z = clo.z * fr.z - chi.z * fi.z;  rhi.z = clo.z * fi.z + chi.z * fr.z;
            rlo.w = clo.w * fr.w - chi.w * fi.w;  rhi.w = clo.w * fi.w + chi.w * fr.w;
            if (sel == 0) {
                uint2 plo = { h2bits(__floats2half2_rn(rlo.x * scale, rlo.y * scale)),
                              h2bits(__floats2half2_rn(rlo.z * scale, rlo.w * scale)) };
                uint2 phi = { h2bits(__floats2half2_rn(rhi.x * scale, rhi.y * scale)),
                              h2bits(__floats2half2_rn(rhi.z * scale, rhi.w * scale)) };
                *(uint2*)&qh[hmaj]      = plo;
                *(uint2*)&qh[hmaj + 64] = phi;
            } else {
                size_t ko = ((size_t)bs * HH + h) * DD + quad;
                *(float4*)&out_k[ko]      = rlo;
                *(float4*)&out_k[ko + 64] = rhi;
                uint2 plo = { h2bits(__floats2half2_rn(rlo.x, rlo.y)),
                              h2bits(__floats2half2_rn(rlo.z, rlo.w)) };
                uint2 phi = { h2bits(__floats2half2_rn(rhi.x, rhi.y)),
                              h2bits(__floats2half2_rn(rhi.z, rhi.w)) };
                *(uint2*)&kh[hmaj]      = plo;
                *(uint2*)&kh[hmaj + 64] = phi;
            }
        }
    }
}

// ============================================================================
// Flash attention, fp16 mma.sync + ldmatrix(+trans for V) + cp.async.
// BM=128 (8 warps x 16), BN=128. Q/K/V all half head-major [B,H,S,D].
// Q fragments hoisted; P register-resident. Causal; heavy tiles first.
// ============================================================================
#define FSTR 136   // halves: row stride (272B, odd 16B count)
#define FA_KB   (128 * FSTR)             // K stage, halves
#define FA_VB   (128 * FSTR)             // V stage, halves
#define FA_BYTES ((128*FSTR /*Q*/ + 2*FA_KB + 2*FA_VB) * 2)   // 174080 B

__global__ __launch_bounds__(256, 1)
void flash_attn(const __half* __restrict__ qh,
                const __half* __restrict__ kh,
                const __half* __restrict__ vh,
                const float* __restrict__ mask,
                __half* __restrict__ attn_out) {
    extern __shared__ __half smh[];
    __half* Qs  = smh;                    // [128][FSTR]
    __half* Ks0 = Qs + 128 * FSTR;        // [2][128][FSTR]  rows = kv pos
    __half* Vs0 = Ks0 + 2 * FA_KB;        // [2][128][FSTR]  rows = kv pos

    const int qb = (int)gridDim.x - 1 - (int)blockIdx.x;
    const int h = blockIdx.y, b = blockIdx.z;
    const int tid = threadIdx.x, w = tid >> 5, l = tid & 31;
    const int lr = l >> 2, lc = l & 3;

    const int mat = l >> 3;
    const uint32_t sQ = smem_u32(Qs), sK = smem_u32(Ks0);
    const uint32_t sV = smem_u32(Vs0);
    const uint32_t qFrag = sQ + (uint32_t)(((w * 16 + (mat & 1) * 8 + (l & 7)) * FSTR)
                                           + (mat >> 1) * 8) * 2;
    const uint32_t kFrag = sK + (uint32_t)((((mat >> 1) * 8 + (l & 7)) * FSTR)
                                           + (mat & 1) * 8) * 2;
    const uint32_t vFrag = sV + (uint32_t)((((mat & 1) * 8 + (l & 7)) * FSTR)
                                           + (mat >> 1) * 8) * 2;

    const __half* qrh = qh + ((size_t)(b * HH + h) * SS) * DD;
    const __half* krh = kh + ((size_t)(b * HH + h) * SS) * DD;
    const __half* vrh = vh + ((size_t)(b * HH + h) * SS) * DD;

    auto issue_kv = [&](int buf, int kb) {
        const uint32_t kBase = sK + (uint32_t)buf * (FA_KB * 2);
        const uint32_t vBase = sV + (uint32_t)buf * (FA_VB * 2);
#pragma unroll
        for (int j = 0; j < 8; j++) {
            int t = tid + j * 256;
            int r = t >> 4, c8 = t & 15;
            cp16(kBase + (uint32_t)(r * FSTR + c8 * 8) * 2,
                 &krh[(size_t)(kb * 128 + r) * DD + c8 * 8]);
        }
#pragma unroll
        for (int j = 0; j < 8; j++) {
            int t = tid + j * 256;
            int r = t >> 4, c8 = t & 15;
            cp16(vBase + (uint32_t)(r * FSTR + c8 * 8) * 2,
                 &vrh[(size_t)(kb * 128 + r) * DD + c8 * 8]);
        }
    };

#pragma unroll
    for (int j = 0; j < 8; j++) {
        int t = tid + j * 256;
        int r = t >> 4, c8 = t & 15;
        cp16(sQ + (uint32_t)(r * FSTR + c8 * 8) * 2,
             &qrh[(size_t)(qb * 128 + r) * DD + c8 * 8]);
    }
    CP_COMMIT();
    issue_kv(0, 0);
    CP_COMMIT();
    CP_WAIT0();
    __syncthreads();

    uint32_t qf[8][4];
#pragma unroll
    for (int ks = 0; ks < 8; ks++)
        ldsm_x4(qf[ks], qFrag + ks * 32);

    float O[16][4];
#pragma unroll
    for (int nt = 0; nt < 16; nt++)
#pragma unroll
        for (int i = 0; i < 4; i++) O[nt][i] = 0.f;
    float m_lo = -INFINITY, m_hi = -INFINITY, l_lo = 0.f, l_hi = 0.f;

    const int nKV = qb + 1;

    for (int kb = 0; kb < nKV; kb++) {
        const int buf = kb & 1;
        if (kb > 0) {
            CP_WAIT0();
            __syncthreads();
        }
        if (kb + 1 < nKV) {
            issue_kv(buf ^ 1, kb + 1);
            CP_COMMIT();
        }

        const uint32_t kOff = (uint32_t)buf * (FA_KB * 2);
        const uint32_t vOff = (uint32_t)buf * (FA_VB * 2);

        float S[16][4];
#pragma unroll
        for (int nt = 0; nt < 16; nt++)
#pragma unroll
            for (int i = 0; i < 4; i++) S[nt][i] = 0.f;
#pragma unroll
        for (int ks = 0; ks < 8; ks++) {
#pragma unroll
            for (int p = 0; p < 8; p++) {
                uint32_t r[4];
                ldsm_x4(r, kFrag + kOff + ks * 32 + p * (16 * FSTR * 2));
                mma_f16(S[2 * p], qf[ks], r);
                mma_f16(S[2 * p + 1], qf[ks], r + 2);
            }
        }

        if (kb == qb) {
            const int m_glo = qb * 128 + w * 16 + lr;
            const float* mr0 = &mask[((size_t)b * SS + m_glo) * SS + kb * 128];
            const float* mr1 = mr0 + 8 * SS;
#pragma unroll
            for (int nt = 0; nt < 16; nt++) {
                float2 q0 = *(const float2*)&mr0[nt * 8 + lc * 2];
                float2 q1 = *(const float2*)&mr1[nt * 8 + lc * 2];
                S[nt][0] += q0.x; S[nt][1] += q0.y;
                S[nt][2] += q1.x; S[nt][3] += q1.y;
            }
        }

        float bm_lo = -INFINITY, bm_hi = -INFINITY;
#pragma unroll
        for (int nt = 0; nt < 16; nt++) {
            bm_lo = fmaxf(bm_lo, fmaxf(S[nt][0], S[nt][1]));
            bm_hi = fmaxf(bm_hi, fmaxf(S[nt][2], S[nt][3]));
        }
        bm_lo = fmaxf(bm_lo, __shfl_xor_sync(0xffffffff, bm_lo, 1));
        bm_lo = fmaxf(bm_lo, __shfl_xor_sync(0xffffffff, bm_lo, 2));
        bm_hi = fmaxf(bm_hi, __shfl_xor_sync(0xffffffff, bm_hi, 1));
        bm_hi = fmaxf(bm_hi, __shfl_xor_sync(0xffffffff, bm_hi, 2));
        float mn_lo = fmaxf(m_lo, bm_lo);
        float mn_hi = fmaxf(m_hi, bm_hi);

        float rs_lo = 0.f, rs_hi = 0.f;
#pragma unroll
        for (int nt = 0; nt < 16; nt++) {
            S[nt][0] = __expf(S[nt][0] - mn_lo);
            S[nt][1] = __expf(S[nt][1] - mn_lo);
            S[nt][2] = __expf(S[nt][2] - mn_hi);
            S[nt][3] = __expf(S[nt][3] - mn_hi);
            rs_lo += S[nt][0] + S[nt][1];
            rs_hi += S[nt][2] + S[nt][3];
        }
        rs_lo += __shfl_xor_sync(0xffffffff, rs_lo, 1);
        rs_lo += __shfl_xor_sync(0xffffffff, rs_lo, 2);
        rs_hi += __shfl_xor_sync(0xffffffff, rs_hi, 1);
        rs_hi += __shfl_xor_sync(0xffffffff, rs_hi, 2);

        float al_lo = __expf(m_lo - mn_lo);
        float al_hi = __expf(m_hi - mn_hi);
        l_lo = l_lo * al_lo + rs_lo;
        l_hi = l_hi * al_hi + rs_hi;
        m_lo = mn_lo; m_hi = mn_hi;
#pragma unroll
        for (int nt = 0; nt < 16; nt++) {
            O[nt][0] *= al_lo; O[nt][1] *= al_lo;
            O[nt][2] *= al_hi; O[nt][3] *= al_hi;
        }

#pragma unroll
        for (int ks = 0; ks < 8; ks++) {
            uint32_t af[4];
            af[0] = h2bits(__floats2half2_rn(S[2 * ks][0],     S[2 * ks][1]));
            af[1] = h2bits(__floats2half2_rn(S[2 * ks][2],     S[2 * ks][3]));
            af[2] = h2bits(__floats2half2_rn(S[2 * ks + 1][0], S[2 * ks + 1][1]));
            af[3] = h2bits(__floats2half2_rn(S[2 * ks + 1][2], S[2 * ks + 1][3]));
#pragma unroll
            for (int p = 0; p < 8; p++) {
                uint32_t r[4];
                ldsm_x4_t(r, vFrag + vOff + ks * (16 * FSTR * 2) + p * 32);
                mma_f16(O[2 * p], af, r);
                mma_f16(O[2 * p + 1], af, r + 2);
            }
        }
    }

    const float inv_lo = 1.0f / l_lo, inv_hi = 1.0f / l_hi;
    const int m0 = qb * 128 + w * 16 + lr;
#pragma unroll
    for (int nt = 0; nt < 16; nt++) {
        int d = nt * 8 + lc * 2;
        __half2 v0 = __floats2half2_rn(O[nt][0] * inv_lo, O[nt][1] * inv_lo);
        __half2 v1 = __floats2half2_rn(O[nt][2] * inv_hi, O[nt][3] * inv_hi);
        *(__half2*)&attn_out[(((size_t)b * SS + m0) * HH + h) * DD + d] = v0;
        *(__half2*)&attn_out[(((size_t)b * SS + m0 + 8) * HH + h) * DD + d] = v1;
    }
}

// ---------------- launch ----------------------------------------------------
extern "C" void kernel_launch(void* const* d_in, const int* in_sizes, int n_in,
                              void* d_out, int out_size) {
    const float* x      = (const float*)d_in[0];
    const float* f_r    = (const float*)d_in[1];
    const float* f_i    = (const float*)d_in[2];
    const float* mask   = (const float*)d_in[3];
    const float* W_qkv  = (const float*)d_in[4];
    const float* b_qkv  = (const float*)d_in[5];
    const float* W_o    = (const float*)d_in[6];

    float* out   = (float*)d_out;
    float* out_k = out   + (size_t)BB * SS * NSTATE;
    float* out_v = out_k + (size_t)BB * SS * HH * DD;

    __half* attnh = nullptr; cudaGetSymbolAddress((void**)&attnh, g_attnh);
    __half* xh = nullptr;    cudaGetSymbolAddress((void**)&xh,    g_xh);
    __half* wqh = nullptr;   cudaGetSymbolAddress((void**)&wqh,   g_wqh);
    __half* woh = nullptr;   cudaGetSymbolAddress((void**)&woh,   g_woh);
    __half* qh = nullptr;    cudaGetSymbolAddress((void**)&qh,    g_qh);
    __half* kh = nullptr;    cudaGetSymbolAddress((void**)&kh,    g_kh);
    __half* vh = nullptr;    cudaGetSymbolAddress((void**)&vh,    g_vh);

    const int M = BB * SS;   // 4096

    cudaFuncSetAttribute(gemm_mma, cudaFuncAttributeMaxDynamicSharedMemorySize,
                         G_SMEM);
    cudaFuncSetAttribute(gemm_qkv_rope,
                         cudaFuncAttributeMaxDynamicSharedMemorySize, G_SMEM);
    cudaFuncSetAttribute(flash_attn, cudaFuncAttributeMaxDynamicSharedMemorySize,
                         FA_BYTES);

    // 0) pre-round GEMM inputs to fp16
    {
        int n4x = (M * NSTATE) / 4;
        round_half<<<(n4x + 255) / 256, 256>>>(x, xh, n4x);
        int n4q = (QKV_W * NSTATE) / 4;
        round_half<<<(n4q + 255) / 256, 256>>>(W_qkv, wqh, n4q);
        int n4o = (NSTATE * NSTATE) / 4;
        round_half<<<(n4o + 255) / 256, 256>>>(W_o, woh, n4o);
    }

    // 1) QKV projection with fused bias + RoPE + scatter (vectorized epilogue)
    gemm_qkv_rope<<<dim3(QKV_W / 128, M / 128), 128, G_SMEM>>>(
        xh, wqh, b_qkv, f_r, f_i, out_k, out_v, qh, kh, vh);
    // 2) attention (fp16 mma, trans-ldmatrix V, register P, cp.async)
    flash_attn<<<dim3(SS / 128, HH, BB), 256, FA_BYTES>>>(qh, kh, vh,
                                                          mask, attnh);
    // 3) output projection
    gemm_mma<<<dim3(NSTATE / 128, M / 128), 128, G_SMEM>>>(
        attnh, woh, out, M, NSTATE, NSTATE);
}

// round 17
// speedup vs baseline: 1.1518x; 1.0179x over previous
#include <cuda_runtime.h>
#include <cuda_fp16.h>
#include <cstdint>
#include <math.h>

// Problem constants
#define BB 2
#define SS 2048
#define HH 16
#define DD 128
#define NSTATE 2048
#define QKV_W (3*HH*DD)   // 6144

// ---------------- scratch (device globals; no runtime alloc) ----------------
__device__ __half g_attnh[(size_t)BB * SS * HH * DD]; // attn out, half
__device__ __half g_xh[(size_t)BB * SS * NSTATE];     // x half
__device__ __half g_wqh[(size_t)QKV_W * NSTATE];      // W_qkv half
__device__ __half g_woh[(size_t)NSTATE * NSTATE];     // W_o half
__device__ __half g_qh[(size_t)BB * HH * SS * DD];    // q half prescaled [B,H,S,D]
__device__ __half g_kh[(size_t)BB * HH * SS * DD];    // k half [B,H,S,D]
__device__ __half g_vh[(size_t)BB * HH * SS * DD];    // v half [B,H,S,D]

// ---------------- helpers ----------------------------------------------------
__device__ __forceinline__ uint32_t smem_u32(const void* p) {
    uint32_t a;
    asm("{ .reg .u64 t; cvta.to.shared.u64 t, %1; cvt.u32.u64 %0, t; }"
        : "=r"(a) : "l"(p));
    return a;
}
__device__ __forceinline__ void mma_f16(float* c, const uint32_t* a,
                                        const uint32_t* b) {
    asm volatile(
        "mma.sync.aligned.m16n8k16.row.col.f32.f16.f16.f32 "
        "{%0,%1,%2,%3}, {%4,%5,%6,%7}, {%8,%9}, {%0,%1,%2,%3};\n"
        : "+f"(c[0]), "+f"(c[1]), "+f"(c[2]), "+f"(c[3])
        : "r"(a[0]), "r"(a[1]), "r"(a[2]), "r"(a[3]), "r"(b[0]), "r"(b[1]));
}
__device__ __forceinline__ void ldsm_x4(uint32_t* r, uint32_t addr) {
    asm volatile("ldmatrix.sync.aligned.m8n8.x4.shared.b16 {%0,%1,%2,%3}, [%4];"
                 : "=r"(r[0]), "=r"(r[1]), "=r"(r[2]), "=r"(r[3]) : "r"(addr));
}
__device__ __forceinline__ void ldsm_x4_t(uint32_t* r, uint32_t addr) {
    asm volatile("ldmatrix.sync.aligned.m8n8.x4.trans.shared.b16 {%0,%1,%2,%3}, [%4];"
                 : "=r"(r[0]), "=r"(r[1]), "=r"(r[2]), "=r"(r[3]) : "r"(addr));
}
__device__ __forceinline__ void cp16(uint32_t s, const void* g) {
    asm volatile("cp.async.cg.shared.global [%0], [%1], 16;"
                 :: "r"(s), "l"(g) : "memory");
}
__device__ __forceinline__ uint32_t h2bits(__half2 h) {
    return *(uint32_t*)&h;
}
#define CP_COMMIT() asm volatile("cp.async.commit_group;" ::: "memory")
#define CP_WAIT2()  asm volatile("cp.async.wait_group 2;"  ::: "memory")
#define CP_WAIT0()  asm volatile("cp.async.wait_group 0;"  ::: "memory")

// ---------------- fused fp32 -> fp16 round pass (all three tensors) ----------
__global__ void round3(const float* __restrict__ s0, __half* __restrict__ d0, int n0,
                       const float* __restrict__ s1, __half* __restrict__ d1, int n1,
                       const float* __restrict__ s2, __half* __restrict__ d2, int n2) {
    int i = blockIdx.x * blockDim.x + threadIdx.x;
    const float* s; __half* d; int j;
    if (i < n0)            { s = s0; d = d0; j = i; }
    else if (i < n0 + n1)  { s = s1; d = d1; j = i - n0; }
    else if (i < n0 + n1 + n2) { s = s2; d = d2; j = i - n0 - n1; }
    else return;
    float4 v = ((const float4*)s)[j];
    __half2 h0 = __floats2half2_rn(v.x, v.y);
    __half2 h1 = __floats2half2_rn(v.z, v.w);
    uint2 o = { *(uint32_t*)&h0, *(uint32_t*)&h1 };
    ((uint2*)d)[j] = o;
}

// ============================================================================
// Shared GEMM config: block 128x128, BK=32 halves, 4 warps (2x2), 64x64 warp
// tiles, 4-stage cp.async ring, TPH=40, pipelined B-fragment loads. 2 CTAs/SM.
// ============================================================================
#define TPH 40                                // halves; 80B row (5x16B, odd)
#define G_NSTG 4
#define G_AB (128 * TPH * 2)                  // 10240 B per operand tile
#define G_STG (2 * G_AB)                      // 20480 B per stage
#define G_SMEM (G_NSTG * G_STG)               // 81920 B

__device__ __forceinline__ void gemm_issue(uint32_t sbase,
                                           const __half* __restrict__ A,
                                           const __half* __restrict__ B,
                                           int m0, int n0, int K, int k0,
                                           int tid) {
#pragma unroll
    for (int j = 0; j < 4; j++) {               // 512 chunks of A
        int t = tid + j * 128;
        int row = t >> 2, seg = t & 3;
        cp16(sbase + (uint32_t)(row * TPH + seg * 8) * 2,
             &A[(size_t)(m0 + row) * K + k0 + seg * 8]);
    }
    const uint32_t sB = sbase + G_AB;
#pragma unroll
    for (int j = 0; j < 4; j++) {               // 512 chunks of B
        int t = tid + j * 128;
        int row = t >> 2, seg = t & 3;
        cp16(sB + (uint32_t)(row * TPH + seg * 8) * 2,
             &B[(size_t)(n0 + row) * K + k0 + seg * 8]);
    }
}

// Mainloop with B double-buffered ldsm pipeline (acc[4][8][4] in caller regs)
#define GEMM_MAINLOOP(A, B, m0, n0, K)                                        \
    const int NC = (K) / 32;                                                  \
    _Pragma("unroll")                                                         \
    for (int s = 0; s < G_NSTG - 1; s++) {                                    \
        gemm_issue(sb + s * G_STG, A, B, m0, n0, K, s * 32, tid);             \
        CP_COMMIT();                                                          \
    }                                                                         \
    for (int c = 0; c < NC; c++) {                                            \
        CP_WAIT2();                                                           \
        __syncthreads();                                                      \
        const int nc = c + G_NSTG - 1;                                        \
        if (nc < NC)                                                          \
            gemm_issue(sb + (nc % G_NSTG) * G_STG, A, B, m0, n0, K,           \
                       nc * 32, tid);                                         \
        CP_COMMIT();                                                          \
        const uint32_t st = sb + (c % G_NSTG) * G_STG;                        \
        _Pragma("unroll")                                                     \
        for (int kk = 0; kk < 2; kk++) {                                      \
            uint32_t af[4][4];                                                \
            _Pragma("unroll")                                                 \
            for (int mt = 0; mt < 4; mt++)                                    \
                ldsm_x4(af[mt], st + aOff + kk * 32 + mt * (16 * TPH * 2));   \
            uint32_t rb[2][4];                                                \
            ldsm_x4(rb[0], st + bOff + kk * 32);                              \
            _Pragma("unroll")                                                 \
            for (int p = 0; p < 4; p++) {                                     \
                if (p < 3)                                                    \
                    ldsm_x4(rb[(p + 1) & 1],                                  \
                            st + bOff + kk * 32 + (p + 1) * (16 * TPH * 2));  \
                const uint32_t* r = rb[p & 1];                                \
                _Pragma("unroll")                                             \
                for (int mt = 0; mt < 4; mt++) {                              \
                    mma_f16(acc[mt][2 * p],     af[mt], r);                   \
                    mma_f16(acc[mt][2 * p + 1], af[mt], r + 2);               \
                }                                                             \
            }                                                                 \
        }                                                                     \
    }

// ============================================================================
// Output-projection GEMM (NT): C fp32 = A @ B^T
// ============================================================================
__global__ __launch_bounds__(128, 2)
void gemm_mma(const __half* __restrict__ A, const __half* __restrict__ B,
              float* __restrict__ C, int M, int N, int K) {
    extern __shared__ uint32_t dynsm[];
    const uint32_t sb = smem_u32(dynsm);

    const int tid = threadIdx.x;
    const int w = tid >> 5, l = tid & 31;
    const int lr = l >> 2, lc = l & 3;
    const int wm = w >> 1, wn = w & 1;
    const int m0 = blockIdx.y * 128, n0 = blockIdx.x * 128;
    const int mat = l >> 3;

    const uint32_t aOff = (uint32_t)(((wm * 64 + (mat & 1) * 8 + (l & 7)) * TPH)
                                     + (mat >> 1) * 8) * 2;
    const uint32_t bOff = G_AB
                        + (uint32_t)(((wn * 64 + (mat >> 1) * 8 + (l & 7)) * TPH)
                                     + (mat & 1) * 8) * 2;

    float acc[4][8][4];
#pragma unroll
    for (int mt = 0; mt < 4; mt++)
#pragma unroll
        for (int nt = 0; nt < 8; nt++)
#pragma unroll
            for (int i = 0; i < 4; i++) acc[mt][nt][i] = 0.f;

    GEMM_MAINLOOP(A, B, m0, n0, K)

#pragma unroll
    for (int mt = 0; mt < 4; mt++) {
        int m = m0 + wm * 64 + mt * 16 + lr;
#pragma unroll
        for (int nt = 0; nt < 8; nt++) {
            int n = n0 + wn * 64 + nt * 8 + lc * 2;
            float2 v0 = { acc[mt][nt][0], acc[mt][nt][1] };
            float2 v1 = { acc[mt][nt][2], acc[mt][nt][3] };
            *(float2*)&C[(size_t)m * N + n] = v0;
            *(float2*)&C[(size_t)(m + 8) * N + n] = v1;
        }
    }
}

// ============================================================================
// QKV GEMM with fused bias + RoPE epilogue (vectorized, 16 iters/thread).
// ============================================================================
#define CSTR 132   // fp32 stage row stride

__global__ __launch_bounds__(128, 2)
void gemm_qkv_rope(const __half* __restrict__ A, const __half* __restrict__ B,
                   const float* __restrict__ bias,
                   const float* __restrict__ f_r, const float* __restrict__ f_i,
                   float* __restrict__ out_k, float* __restrict__ out_v,
                   __half* __restrict__ qh, __half* __restrict__ kh,
                   __half* __restrict__ vh) {
    extern __shared__ uint32_t dynsm[];
    const uint32_t sb = smem_u32(dynsm);
    const int K = NSTATE;

    const int tid = threadIdx.x;
    const int w = tid >> 5, l = tid & 31;
    const int lr = l >> 2, lc = l & 3;
    const int wm = w >> 1, wn = w & 1;
    const int m0 = blockIdx.y * 128, n0 = blockIdx.x * 128;
    const int sel = blockIdx.x >> 4;             // 0=q, 1=k, 2=v
    const int h   = blockIdx.x & 15;
    const int mat = l >> 3;

    const uint32_t aOff = (uint32_t)(((wm * 64 + (mat & 1) * 8 + (l & 7)) * TPH)
                                     + (mat >> 1) * 8) * 2;
    const uint32_t bOff = G_AB
                        + (uint32_t)(((wn * 64 + (mat >> 1) * 8 + (l & 7)) * TPH)
                                     + (mat & 1) * 8) * 2;

    float acc[4][8][4];
#pragma unroll
    for (int mt = 0; mt < 4; mt++)
#pragma unroll
        for (int nt = 0; nt < 8; nt++)
#pragma unroll
            for (int i = 0; i < 4; i++) acc[mt][nt][i] = 0.f;

    GEMM_MAINLOOP(A, B, m0, n0, K)

    // ---- epilogue: bias, stage fp32 tile to smem ----
    __syncthreads();
    float* Ct = (float*)dynsm;        // [128][CSTR]
#pragma unroll
    for (int mt = 0; mt < 4; mt++) {
        int ml = wm * 64 + mt * 16 + lr;
#pragma unroll
        for (int nt = 0; nt < 8; nt++) {
            int nl = wn * 64 + nt * 8 + lc * 2;
            float bx = bias[n0 + nl], by = bias[n0 + nl + 1];
            Ct[ml * CSTR + nl]           = acc[mt][nt][0] + bx;
            Ct[ml * CSTR + nl + 1]       = acc[mt][nt][1] + by;
            Ct[(ml + 8) * CSTR + nl]     = acc[mt][nt][2] + bx;
            Ct[(ml + 8) * CSTR + nl + 1] = acc[mt][nt][3] + by;
        }
    }
    __syncthreads();

    // ---- rope + scatter: thread = (rgroup, quad); 16 float4 iterations ----
    const float scale = 0.08838834764831845f;    // 1/sqrt(128)
    const int quad = (tid & 15) * 4;
    const int rg   = tid >> 4;
#pragma unroll 4
    for (int i = 0; i < 16; i++) {
        int r = rg * 16 + i;
        int bs = m0 + r;
        int b = bs >> 11, s = bs & (SS - 1);
        float4 clo = *(float4*)&Ct[r * CSTR + quad];
        float4 chi = *(float4*)&Ct[r * CSTR + quad + 64];
        size_t hmaj = (((size_t)(b * HH + h) * SS) + s) * DD + quad;
        if (sel == 2) {
            size_t ko = ((size_t)bs * HH + h) * DD + quad;
            *(float4*)&out_v[ko]      = clo;
            *(float4*)&out_v[ko + 64] = chi;
            uint2 plo = { h2bits(__floats2half2_rn(clo.x, clo.y)),
                          h2bits(__floats2half2_rn(clo.z, clo.w)) };
            uint2 phi = { h2bits(__floats2half2_rn(chi.x, chi.y)),
                          h2bits(__floats2half2_rn(chi.z, chi.w)) };
            *(uint2*)&vh[hmaj]      = plo;
            *(uint2*)&vh[hmaj + 64] = phi;
        } else {
            float4 fr = *(const float4*)&f_r[(size_t)bs * 64 + quad];
            float4 fi = *(const float4*)&f_i[(size_t)bs * 64 + quad];
            float4 rlo, rhi;
            rlo.x = clo.x * fr.x - chi.x * fi.x;  rhi.x = clo.x * fi.x + chi.x * fr.x;
            rlo.y = clo.y * fr.y - chi.y * fi.y;  rhi.y = clo.y * fi.y + chi.y * fr.y;
            rlo.z = clo.z * fr.z - chi.z * fi.z;  rhi.z = clo.z * fi.z + chi.z * fr.z;
            rlo.w = clo.w * fr.w - chi.w * fi.w;  rhi.w = clo.w * fi.w + chi.w * fr.w;
            if (sel == 0) {
                uint2 plo = { h2bits(__floats2half2_rn(rlo.x * scale, rlo.y * scale)),
                              h2bits(__floats2half2_rn(rlo.z * scale, rlo.w * scale)) };
                uint2 phi = { h2bits(__floats2half2_rn(rhi.x * scale, rhi.y * scale)),
                              h2bits(__floats2half2_rn(rhi.z * scale, rhi.w * scale)) };
                *(uint2*)&qh[hmaj]      = plo;
                *(uint2*)&qh[hmaj + 64] = phi;
            } else {
                size_t ko = ((size_t)bs * HH + h) * DD + quad;
                *(float4*)&out_k[ko]      = rlo;
                *(float4*)&out_k[ko + 64] = rhi;
                uint2 plo = { h2bits(__floats2half2_rn(rlo.x, rlo.y)),
                              h2bits(__floats2half2_rn(rlo.z, rlo.w)) };
                uint2 phi = { h2bits(__floats2half2_rn(rhi.x, rhi.y)),
                              h2bits(__floats2half2_rn(rhi.z, rhi.w)) };
                *(uint2*)&kh[hmaj]      = plo;
                *(uint2*)&kh[hmaj + 64] = phi;
            }
        }
    }
}

// ============================================================================
// Flash attention, fp16 mma.sync + ldmatrix(+trans V) + cp.async,
// pipelined fragment loads. BM=128 (8 warps x 16), BN=128. Causal; heavy first.
// ============================================================================
#define FSTR 136   // halves: row stride (272B, odd 16B count)
#define FA_KB   (128 * FSTR)             // K stage, halves
#define FA_VB   (128 * FSTR)             // V stage, halves
#define FA_BYTES ((128*FSTR /*Q*/ + 2*FA_KB + 2*FA_VB) * 2)   // 174080 B

__global__ __launch_bounds__(256, 1)
void flash_attn(const __half* __restrict__ qh,
                const __half* __restrict__ kh,
                const __half* __restrict__ vh,
                const float* __restrict__ mask,
                __half* __restrict__ attn_out) {
    extern __shared__ __half smh[];
    __half* Qs  = smh;                    // [128][FSTR]
    __half* Ks0 = Qs + 128 * FSTR;        // [2][128][FSTR]  rows = kv pos
    __half* Vs0 = Ks0 + 2 * FA_KB;        // [2][128][FSTR]  rows = kv pos

    const int qb = (int)gridDim.x - 1 - (int)blockIdx.x;
    const int h = blockIdx.y, b = blockIdx.z;
    const int tid = threadIdx.x, w = tid >> 5, l = tid & 31;
    const int lr = l >> 2, lc = l & 3;

    const int mat = l >> 3;
    const uint32_t sQ = smem_u32(Qs), sK = smem_u32(Ks0);
    const uint32_t sV = smem_u32(Vs0);
    const uint32_t qFrag = sQ + (uint32_t)(((w * 16 + (mat & 1) * 8 + (l & 7)) * FSTR)
                                           + (mat >> 1) * 8) * 2;
    const uint32_t kFrag = sK + (uint32_t)((((mat >> 1) * 8 + (l & 7)) * FSTR)
                                           + (mat & 1) * 8) * 2;
    const uint32_t vFrag = sV + (uint32_t)((((mat & 1) * 8 + (l & 7)) * FSTR)
                                           + (mat >> 1) * 8) * 2;

    const __half* qrh = qh + ((size_t)(b * HH + h) * SS) * DD;
    const __half* krh = kh + ((size_t)(b * HH + h) * SS) * DD;
    const __half* vrh = vh + ((size_t)(b * HH + h) * SS) * DD;

    auto issue_kv = [&](int buf, int kb) {
        const uint32_t kBase = sK + (uint32_t)buf * (FA_KB * 2);
        const uint32_t vBase = sV + (uint32_t)buf * (FA_VB * 2);
#pragma unroll
        for (int j = 0; j < 8; j++) {
            int t = tid + j * 256;
            int r = t >> 4, c8 = t & 15;
            cp16(kBase + (uint32_t)(r * FSTR + c8 * 8) * 2,
                 &krh[(size_t)(kb * 128 + r) * DD + c8 * 8]);
        }
#pragma unroll
        for (int j = 0; j < 8; j++) {
            int t = tid + j * 256;
            int r = t >> 4, c8 = t & 15;
            cp16(vBase + (uint32_t)(r * FSTR + c8 * 8) * 2,
                 &vrh[(size_t)(kb * 128 + r) * DD + c8 * 8]);
        }
    };

#pragma unroll
    for (int j = 0; j < 8; j++) {
        int t = tid + j * 256;
        int r = t >> 4, c8 = t & 15;
        cp16(sQ + (uint32_t)(r * FSTR + c8 * 8) * 2,
             &qrh[(size_t)(qb * 128 + r) * DD + c8 * 8]);
    }
    CP_COMMIT();
    issue_kv(0, 0);
    CP_COMMIT();
    CP_WAIT0();
    __syncthreads();

    uint32_t qf[8][4];
#pragma unroll
    for (int ks = 0; ks < 8; ks++)
        ldsm_x4(qf[ks], qFrag + ks * 32);

    float O[16][4];
#pragma unroll
    for (int nt = 0; nt < 16; nt++)
#pragma unroll
        for (int i = 0; i < 4; i++) O[nt][i] = 0.f;
    float m_lo = -INFINITY, m_hi = -INFINITY, l_lo = 0.f, l_hi = 0.f;

    const int nKV = qb + 1;

    for (int kb = 0; kb < nKV; kb++) {
        const int buf = kb & 1;
        if (kb > 0) {
            CP_WAIT0();
            __syncthreads();
        }
        if (kb + 1 < nKV) {
            issue_kv(buf ^ 1, kb + 1);
            CP_COMMIT();
        }

        const uint32_t kOff = (uint32_t)buf * (FA_KB * 2);
        const uint32_t vOff = (uint32_t)buf * (FA_VB * 2);

        // ---- S = Q K^T (pipelined K fragments) ----
        float S[16][4];
#pragma unroll
        for (int nt = 0; nt < 16; nt++)
#pragma unroll
            for (int i = 0; i < 4; i++) S[nt][i] = 0.f;
#pragma unroll
        for (int ks = 0; ks < 8; ks++) {
            uint32_t rk[2][4];
            ldsm_x4(rk[0], kFrag + kOff + ks * 32);
#pragma unroll
            for (int p = 0; p < 8; p++) {
                if (p < 7)
                    ldsm_x4(rk[(p + 1) & 1],
                            kFrag + kOff + ks * 32 + (p + 1) * (16 * FSTR * 2));
                const uint32_t* r = rk[p & 1];
                mma_f16(S[2 * p], qf[ks], r);
                mma_f16(S[2 * p + 1], qf[ks], r + 2);
            }
        }

        if (kb == qb) {
            const int m_glo = qb * 128 + w * 16 + lr;
            const float* mr0 = &mask[((size_t)b * SS + m_glo) * SS + kb * 128];
            const float* mr1 = mr0 + 8 * SS;
#pragma unroll
            for (int nt = 0; nt < 16; nt++) {
                float2 q0 = *(const float2*)&mr0[nt * 8 + lc * 2];
                float2 q1 = *(const float2*)&mr1[nt * 8 + lc * 2];
                S[nt][0] += q0.x; S[nt][1] += q0.y;
                S[nt][2] += q1.x; S[nt][3] += q1.y;
            }
        }

        float bm_lo = -INFINITY, bm_hi = -INFINITY;
#pragma unroll
        for (int nt = 0; nt < 16; nt++) {
            bm_lo = fmaxf(bm_lo, fmaxf(S[nt][0], S[nt][1]));
            bm_hi = fmaxf(bm_hi, fmaxf(S[nt][2], S[nt][3]));
        }
        bm_lo = fmaxf(bm_lo, __shfl_xor_sync(0xffffffff, bm_lo, 1));
        bm_lo = fmaxf(bm_lo, __shfl_xor_sync(0xffffffff, bm_lo, 2));
        bm_hi = fmaxf(bm_hi, __shfl_xor_sync(0xffffffff, bm_hi, 1));
        bm_hi = fmaxf(bm_hi, __shfl_xor_sync(0xffffffff, bm_hi, 2));
        float mn_lo = fmaxf(m_lo, bm_lo);
        float mn_hi = fmaxf(m_hi, bm_hi);

        float rs_lo = 0.f, rs_hi = 0.f;
#pragma unroll
        for (int nt = 0; nt < 16; nt++) {
            S[nt][0] = __expf(S[nt][0] - mn_lo);
            S[nt][1] = __expf(S[nt][1] - mn_lo);
            S[nt][2] = __expf(S[nt][2] - mn_hi);
            S[nt][3] = __expf(S[nt][3] - mn_hi);
            rs_lo += S[nt][0] + S[nt][1];
            rs_hi += S[nt][2] + S[nt][3];
        }
        rs_lo += __shfl_xor_sync(0xffffffff, rs_lo, 1);
        rs_lo += __shfl_xor_sync(0xffffffff, rs_lo, 2);
        rs_hi += __shfl_xor_sync(0xffffffff, rs_hi, 1);
        rs_hi += __shfl_xor_sync(0xffffffff, rs_hi, 2);

        float al_lo = __expf(m_lo - mn_lo);
        float al_hi = __expf(m_hi - mn_hi);
        l_lo = l_lo * al_lo + rs_lo;
        l_hi = l_hi * al_hi + rs_hi;
        m_lo = mn_lo; m_hi = mn_hi;
#pragma unroll
        for (int nt = 0; nt < 16; nt++) {
            O[nt][0] *= al_lo; O[nt][1] *= al_lo;
            O[nt][2] *= al_hi; O[nt][3] *= al_hi;
        }

        // ---- O += P V (pipelined trans-V fragments) ----
#pragma unroll
        for (int ks = 0; ks < 8; ks++) {
            uint32_t af[4];
            af[0] = h2bits(__floats2half2_rn(S[2 * ks][0],     S[2 * ks][1]));
            af[1] = h2bits(__floats2half2_rn(S[2 * ks][2],     S[2 * ks][3]));
            af[2] = h2bits(__floats2half2_rn(S[2 * ks + 1][0], S[2 * ks + 1][1]));
            af[3] = h2bits(__floats2half2_rn(S[2 * ks + 1][2], S[2 * ks + 1][3]));
            uint32_t rv[2][4];
            ldsm_x4_t(rv[0], vFrag + vOff + ks * (16 * FSTR * 2));
#pragma unroll
            for (int p = 0; p < 8; p++) {
                if (p < 7)
                    ldsm_x4_t(rv[(p + 1) & 1],
                              vFrag + vOff + ks * (16 * FSTR * 2) + (p + 1) * 32);
                const uint32_t* r = rv[p & 1];
                mma_f16(O[2 * p], af, r);
                mma_f16(O[2 * p + 1], af, r + 2);
            }
        }
    }

    const float inv_lo = 1.0f / l_lo, inv_hi = 1.0f / l_hi;
    const int m0 = qb * 128 + w * 16 + lr;
#pragma unroll
    for (int nt = 0; nt < 16; nt++) {
        int d = nt * 8 + lc * 2;
        __half2 v0 = __floats2half2_rn(O[nt][0] * inv_lo, O[nt][1] * inv_lo);
        __half2 v1 = __floats2half2_rn(O[nt][2] * inv_hi, O[nt][3] * inv_hi);
        *(__half2*)&attn_out[(((size_t)b * SS + m0) * HH + h) * DD + d] = v0;
        *(__half2*)&attn_out[(((size_t)b * SS + m0 + 8) * HH + h) * DD + d] = v1;
    }
}

// ---------------- launch ----------------------------------------------------
extern "C" void kernel_launch(void* const* d_in, const int* in_sizes, int n_in,
                              void* d_out, int out_size) {
    const float* x      = (const float*)d_in[0];
    const float* f_r    = (const float*)d_in[1];
    const float* f_i    = (const float*)d_in[2];
    const float* mask   = (const float*)d_in[3];
    const float* W_qkv  = (const float*)d_in[4];
    const float* b_qkv  = (const float*)d_in[5];
    const float* W_o    = (const float*)d_in[6];

    float* out   = (float*)d_out;
    float* out_k = out   + (size_t)BB * SS * NSTATE;
    float* out_v = out_k + (size_t)BB * SS * HH * DD;

    __half* attnh = nullptr; cudaGetSymbolAddress((void**)&attnh, g_attnh);
    __half* xh = nullptr;    cudaGetSymbolAddress((void**)&xh,    g_xh);
    __half* wqh = nullptr;   cudaGetSymbolAddress((void**)&wqh,   g_wqh);
    __half* woh = nullptr;   cudaGetSymbolAddress((void**)&woh,   g_woh);
    __half* qh = nullptr;    cudaGetSymbolAddress((void**)&qh,    g_qh);
    __half* kh = nullptr;    cudaGetSymbolAddress((void**)&kh,    g_kh);
    __half* vh = nullptr;    cudaGetSymbolAddress((void**)&vh,    g_vh);

    const int M = BB * SS;   // 4096

    cudaFuncSetAttribute(gemm_mma, cudaFuncAttributeMaxDynamicSharedMemorySize,
                         G_SMEM);
    cudaFuncSetAttribute(gemm_qkv_rope,
                         cudaFuncAttributeMaxDynamicSharedMemorySize, G_SMEM);
    cudaFuncSetAttribute(flash_attn, cudaFuncAttributeMaxDynamicSharedMemorySize,
                         FA_BYTES);

    // 0) fused pre-round pass (x, W_qkv, W_o -> fp16)
    {
        int n0 = (M * NSTATE) / 4;
        int n1 = (QKV_W * NSTATE) / 4;
        int n2 = (NSTATE * NSTATE) / 4;
        round3<<<(n0 + n1 + n2 + 255) / 256, 256>>>(x, xh, n0, W_qkv, wqh, n1,
                                                    W_o, woh, n2);
    }

    // 1) QKV projection with fused bias + RoPE + scatter
    gemm_qkv_rope<<<dim3(QKV_W / 128, M / 128), 128, G_SMEM>>>(
        xh, wqh, b_qkv, f_r, f_i, out_k, out_v, qh, kh, vh);
    // 2) attention
    flash_attn<<<dim3(SS / 128, HH, BB), 256, FA_BYTES>>>(qh, kh, vh,
                                                          mask, attnh);
    // 3) output projection
    gemm_mma<<<dim3(NSTATE / 128, M / 128), 128, G_SMEM>>>(
        attnh, woh, out, M, NSTATE, NSTATE);
}